// round 6
// baseline (speedup 1.0000x reference)
#include <cuda_runtime.h>
#include <math.h>

// ----------------------------------------------------------------------------
// GridGRU  (D = H = 1024, N = 32, T = 512)
//
// R5: fix graph-upload rule violation (1027 nodes -> 6 nodes) by fusing the
// 512-step scan into ONE persistent kernel with a software grid barrier.
//
//   K1    gates = x @ Wxt + b[:3H]              (16384x1024 @ 1024x3072)
//   SCAN  one kernel, 128 CTAs, 512 steps, 2 grid barriers/step
//   K3    gd = ht @ Whd + b[3H:]                (reuses gates buffer)
//   K4    g2 = sigmoid(gd[:, :2D] + x @ Wxd[:, :2D]) -> ud, rx = rd*x  (fused)
//   K5    h  = x + ud * (tanh(gd[:,2D:] + rx @ Wxd[:,2D:]) - x)        (fused)
//   copy final_ht
// ----------------------------------------------------------------------------

#define D_    1024
#define H_    1024
#define NB    32
#define TT    512
#define MROWS (NB * TT)     // 16384
#define WLD   6144          // weight row stride (2048 x 6144)
#define G3    3072
#define NBLK_SCAN 128

// Scratch (device globals: allocation-free per harness rules)
__device__ float g_gates[(size_t)MROWS * G3];   // gates, then reused as gd
__device__ float g_ht[(size_t)MROWS * H_];      // ht sequence, (n, t, h) row-major
__device__ float g_u [NB * H_];                 // per-step u gate
__device__ float g_rh[NB * H_];                 // per-step r * h_prev
__device__ float g_ud[(size_t)MROWS * D_];      // decoder update gate
__device__ float g_rx[(size_t)MROWS * D_];      // rd * x

// ------------------------- software grid barrier ----------------------------
__device__ unsigned int g_bar_count = 0;
__device__ unsigned int g_bar_gen   = 0;

__device__ __forceinline__ void grid_barrier()
{
    __syncthreads();
    __threadfence();
    if (threadIdx.x == 0) {
        unsigned int gen = *(volatile unsigned int*)&g_bar_gen;
        unsigned int tk  = atomicAdd(&g_bar_count, 1u);
        if (tk == NBLK_SCAN - 1) {
            g_bar_count = 0;
            __threadfence();
            *(volatile unsigned int*)&g_bar_gen = gen + 1u;
        } else {
            while (*(volatile unsigned int*)&g_bar_gen == gen) { __nanosleep(64); }
        }
        __threadfence();
    }
    __syncthreads();
}

// ----------------------------------------------------------------------------
// Persistent scan kernel. 128 CTAs x 256 threads, all co-resident.
// Phase A (per step): gg = sigmoid(gates_t[:, :2H] + h_prev @ Whtg)
//   CTA b handles cols [16b, 16b+16) of 2048; K=1024 split between 2 warp
//   groups (warps 0-3: K[0,512), warps 4-7: K[512,1024)); each warp holds
//   4 columns; partials combined in smem; b<64 -> u, b>=64 -> rh = r*h.
// Phase B: hc = tanh(gates_t[:, 2H:] + rh @ Whtc); h_t = h + u*(hc - h)
//   CTA b handles cols [8b, 8b+8) of 1024; K split across 4 warp groups.
// ----------------------------------------------------------------------------
__global__ void __launch_bounds__(256, 1)
scan_kernel(const float* __restrict__ weight, const float* __restrict__ state)
{
    __shared__ __align__(16) float region0[5248];   // tiles (A: 3136f, B: 5248f)
    __shared__ __align__(16) float region1[2112];   // epilogue staging

    const int tid = threadIdx.x;
    const int b   = blockIdx.x;
    const int n   = tid & 31;
    const int w   = tid >> 5;

    // phase A mapping
    const int gA  = tid >> 7;          // K-half 0/1
    const int lA  = tid & 127;
    const int wgA = w & 3;             // warp-in-group -> 4 cols
    float* hsA = region0;              // [2][32][33]
    float* wsA = region0 + 2 * 32 * 33;// [2][32][16]
    // phase B mapping
    const int gB  = tid >> 6;          // K-quarter 0..3
    const int lB  = tid & 63;
    const int wgB = w & 1;             // warp-in-group -> 4 cols
    float* hsB = region0;              // [4][32][33]
    float* wsB = region0 + 4 * 32 * 33;// [4][32][8]

    const int jbA = b << 4;            // 16 cols in [0,2048)
    const int jbB = b << 3;            // 8 cols in [0,1024)

    for (int t = 0; t < TT; ++t) {
        const float* hp; size_t hstr;
        if (t == 0) { hp = state; hstr = (size_t)H_; }
        else        { hp = g_ht + (size_t)(t - 1) * H_; hstr = (size_t)TT * H_; }

        // =============================== Phase A ===============================
        float a0 = 0.f, a1 = 0.f, a2 = 0.f, a3 = 0.f;
        {
            const int kbase = gA << 9;               // 0 or 512
#pragma unroll 1
            for (int c0 = 0; c0 < 16; ++c0) {
                const int k0 = kbase + (c0 << 5);
#pragma unroll
                for (int i = 0; i < 8; ++i) {        // stage h tile 32k x 32n
                    int idx = lA + (i << 7);
                    int nn = idx >> 5, kk = idx & 31;
                    hsA[(gA * 32 + kk) * 33 + nn] = hp[(size_t)nn * hstr + k0 + kk];
                }
#pragma unroll
                for (int i = 0; i < 4; ++i) {        // stage w tile 32k x 16c
                    int idx = lA + (i << 7);
                    int kk = idx >> 4, c = idx & 15;
                    wsA[(gA * 32 + kk) * 16 + c] =
                        weight[(size_t)(D_ + k0 + kk) * WLD + jbA + c];
                }
                __syncthreads();
#pragma unroll
                for (int kk = 0; kk < 32; ++kk) {
                    float hv = hsA[(gA * 32 + kk) * 33 + n];
                    const float4 w4 =
                        *(const float4*)&wsA[(gA * 32 + kk) * 16 + (wgA << 2)];
                    a0 = fmaf(hv, w4.x, a0);
                    a1 = fmaf(hv, w4.y, a1);
                    a2 = fmaf(hv, w4.z, a2);
                    a3 = fmaf(hv, w4.w, a3);
                }
                __syncthreads();
            }
        }
        {   // combine + epilogue
            float* paccA = region1;          // [16][33]
            float* gsm   = region1 + 528;    // [16][33]
            float* hpe   = region1 + 1056;   // [16][33]
            float* sout  = region1 + 1584;   // [16][33]
            if (gA == 1) {
                paccA[(wgA * 4 + 0) * 33 + n] = a0;
                paccA[(wgA * 4 + 1) * 33 + n] = a1;
                paccA[(wgA * 4 + 2) * 33 + n] = a2;
                paccA[(wgA * 4 + 3) * 33 + n] = a3;
            }
#pragma unroll
            for (int i = 0; i < 2; ++i) {    // stage gates (coalesced 64B rows)
                int idx = tid + (i << 8);
                int c = idx & 15, nn = idx >> 4;
                gsm[c * 33 + nn] =
                    g_gates[(size_t)nn * TT * G3 + (size_t)t * G3 + jbA + c];
            }
            if (b >= 64) {                   // stage h_prev for r-cols
#pragma unroll
                for (int i = 0; i < 2; ++i) {
                    int idx = tid + (i << 8);
                    int c = idx & 15, nn = idx >> 4;
                    hpe[c * 33 + nn] = hp[(size_t)nn * hstr + (jbA - H_) + c];
                }
            }
            __syncthreads();
            if (gA == 0) {
                float av[4] = {a0, a1, a2, a3};
#pragma unroll
                for (int c = 0; c < 4; ++c) {
                    int cc = wgA * 4 + c;
                    float z = av[c] + paccA[cc * 33 + n] + gsm[cc * 33 + n];
                    float s = 1.f / (1.f + expf(-z));
                    float o = (b < 64) ? s : s * hpe[cc * 33 + n];
                    sout[cc * 33 + n] = o;
                }
            }
            __syncthreads();
            {   // coalesced store of u / rh
                float* dst = (b < 64) ? g_u : g_rh;
                const int jb0 = (b < 64) ? jbA : (jbA - H_);
#pragma unroll
                for (int i = 0; i < 2; ++i) {
                    int idx = tid + (i << 8);
                    int c = idx & 15, nn = idx >> 4;
                    dst[nn * H_ + jb0 + c] = sout[c * 33 + nn];
                }
            }
        }
        grid_barrier();

        // =============================== Phase B ===============================
        float b0 = 0.f, b1 = 0.f, b2 = 0.f, b3 = 0.f;
        {
            const int kbase = gB << 8;               // 0,256,512,768
#pragma unroll 1
            for (int c0 = 0; c0 < 8; ++c0) {
                const int k0 = kbase + (c0 << 5);
#pragma unroll
                for (int i = 0; i < 16; ++i) {       // stage rh tile 32k x 32n
                    int idx = lB + (i << 6);
                    int nn = idx >> 5, kk = idx & 31;
                    hsB[(gB * 32 + kk) * 33 + nn] = g_rh[nn * H_ + k0 + kk];
                }
#pragma unroll
                for (int i = 0; i < 4; ++i) {        // stage w tile 32k x 8c
                    int idx = lB + (i << 6);
                    int kk = idx >> 3, c = idx & 7;
                    wsB[(gB * 32 + kk) * 8 + c] =
                        weight[(size_t)(D_ + k0 + kk) * WLD + 2 * H_ + jbB + c];
                }
                __syncthreads();
#pragma unroll
                for (int kk = 0; kk < 32; ++kk) {
                    float hv = hsB[(gB * 32 + kk) * 33 + n];
                    const float4 w4 =
                        *(const float4*)&wsB[(gB * 32 + kk) * 8 + (wgB << 2)];
                    b0 = fmaf(hv, w4.x, b0);
                    b1 = fmaf(hv, w4.y, b1);
                    b2 = fmaf(hv, w4.z, b2);
                    b3 = fmaf(hv, w4.w, b3);
                }
                __syncthreads();
            }
        }
        {   // combine + epilogue
            float* paccB = region1;          // [3][8][33] = 792
            float* gsm2  = region1 + 792;    // [8][33]
            float* hpb   = region1 + 1056;   // [8][33]
            float* ub    = region1 + 1320;   // [8][33]
            float* hout  = region1 + 1584;   // [8][33]
            if (gB > 0) {
                float* p = paccB + (gB - 1) * 264;
                p[(wgB * 4 + 0) * 33 + n] = b0;
                p[(wgB * 4 + 1) * 33 + n] = b1;
                p[(wgB * 4 + 2) * 33 + n] = b2;
                p[(wgB * 4 + 3) * 33 + n] = b3;
            }
            {   // stage gates / h_prev / u (coalesced 32B rows)
                int c = tid & 7, nn = tid >> 3;
                gsm2[c * 33 + nn] =
                    g_gates[(size_t)nn * TT * G3 + (size_t)t * G3 + 2 * H_ + jbB + c];
                hpb[c * 33 + nn] = hp[(size_t)nn * hstr + jbB + c];
                ub[c * 33 + nn]  = g_u[nn * H_ + jbB + c];
            }
            __syncthreads();
            if (gB == 0) {
                float bv[4] = {b0, b1, b2, b3};
#pragma unroll
                for (int c = 0; c < 4; ++c) {
                    int cc = wgB * 4 + c;
                    float z = bv[c] + paccB[cc * 33 + n] + paccB[264 + cc * 33 + n]
                            + paccB[528 + cc * 33 + n] + gsm2[cc * 33 + n];
                    float hc = tanhf(z);
                    float hv = hpb[cc * 33 + n];
                    float u  = ub[cc * 33 + n];
                    hout[cc * 33 + n] = fmaf(u, hc - hv, hv);
                }
            }
            __syncthreads();
            {   // coalesced store of h_t
                int c = tid & 7, nn = tid >> 3;
                g_ht[(size_t)nn * TT * H_ + (size_t)t * H_ + jbB + c] =
                    hout[c * 33 + nn];
            }
        }
        grid_barrier();
    }
}

// ----------------------------------------------------------------------------
// Big GEMM: C(M x Ncols) = A(M x 1024) @ B(1024 x Ncols), B strided into weight.
// 128x128 block tile, BK=8, 256 threads, 8x8 per-thread microtile.
// MODE 0: C = acc + bias[col]
// MODE 1: s = sigmoid(gd[m, col] + acc); col<D -> ud, else rx = s * x
// MODE 2: hcd = tanh(gd[m, 2D+col] + acc); C = x + ud*(hcd - x)
// ----------------------------------------------------------------------------
template <int MODE>
__global__ void __launch_bounds__(256)
sgemm_k(const float* __restrict__ A, int lda,
        const float* __restrict__ B, int ldb,
        const float* __restrict__ bias,
        float* __restrict__ C, int ldc,
        const float* __restrict__ gdp,
        const float* __restrict__ xp,
        float* __restrict__ udp,
        float* __restrict__ rxp)
{
    __shared__ float As[8][128];
    __shared__ float Bs[8][128];

    const int tid     = threadIdx.x;
    const int rowBase = blockIdx.y << 7;
    const int colBase = blockIdx.x << 7;

    const int a_row = tid >> 1;
    const int a_k   = (tid & 1) << 2;
    const int b_k   = tid >> 5;
    const int b_col = (tid & 31) << 2;
    const int tr    = (tid >> 4) << 3;
    const int tc    = (tid & 15) << 3;

    const float* Aptr = A + (size_t)(rowBase + a_row) * lda + a_k;
    const float* Bptr = B + (size_t)b_k * ldb + colBase + b_col;

    float acc[8][8];
#pragma unroll
    for (int i = 0; i < 8; ++i)
#pragma unroll
        for (int j = 0; j < 8; ++j) acc[i][j] = 0.f;

#pragma unroll 1
    for (int k0 = 0; k0 < 1024; k0 += 8) {
        float4 av = *(const float4*)(Aptr + k0);
        float4 bv = *(const float4*)(Bptr + (size_t)k0 * ldb);
        As[a_k + 0][a_row] = av.x;
        As[a_k + 1][a_row] = av.y;
        As[a_k + 2][a_row] = av.z;
        As[a_k + 3][a_row] = av.w;
        *(float4*)(&Bs[b_k][b_col]) = bv;
        __syncthreads();
#pragma unroll
        for (int kk = 0; kk < 8; ++kk) {
            float ar[8], br[8];
#pragma unroll
            for (int i = 0; i < 8; ++i) ar[i] = As[kk][tr + i];
#pragma unroll
            for (int j = 0; j < 8; ++j) br[j] = Bs[kk][tc + j];
#pragma unroll
            for (int i = 0; i < 8; ++i)
#pragma unroll
                for (int j = 0; j < 8; ++j)
                    acc[i][j] = fmaf(ar[i], br[j], acc[i][j]);
        }
        __syncthreads();
    }

#pragma unroll
    for (int i = 0; i < 8; ++i) {
        const int m = rowBase + tr + i;
#pragma unroll
        for (int j = 0; j < 8; ++j) {
            const int col = colBase + tc + j;
            const float v = acc[i][j];
            if (MODE == 0) {
                C[(size_t)m * ldc + col] = v + bias[col];
            } else if (MODE == 1) {
                float s = 1.f / (1.f + expf(-(gdp[(size_t)m * G3 + col] + v)));
                if (col < D_) {
                    udp[(size_t)m * D_ + col] = s;
                } else {
                    const int d = col - D_;
                    rxp[(size_t)m * D_ + d] = s * xp[(size_t)m * D_ + d];
                }
            } else {  // MODE 2
                float hcd = tanhf(gdp[(size_t)m * G3 + 2 * D_ + col] + v);
                float xv  = xp[(size_t)m * D_ + col];
                C[(size_t)m * D_ + col] =
                    fmaf(udp[(size_t)m * D_ + col], hcd - xv, xv);
            }
        }
    }
}

// final_ht = ht[:, T-1, :]
__global__ void __launch_bounds__(256)
copy_final(float* __restrict__ out)
{
    int i = blockIdx.x * 256 + threadIdx.x;          // 0 .. 32767
    int n = i >> 10, h = i & 1023;
    out[i] = g_ht[(size_t)n * TT * H_ + (size_t)(TT - 1) * H_ + h];
}

// ----------------------------------------------------------------------------
extern "C" void kernel_launch(void* const* d_in, const int* in_sizes, int n_in,
                              void* d_out, int out_size)
{
    const float* x      = (const float*)d_in[0];   // (N, T, D)
    const float* state  = (const float*)d_in[1];   // (N, H)
    const float* weight = (const float*)d_in[2];   // (2048, 6144)
    const float* bias   = (const float*)d_in[3];   // (6144,)
    float*       out    = (float*)d_out;           // h (N,T,D) then final_ht (N,H)

    float *gates, *ht, *ud, *rx;
    cudaGetSymbolAddress((void**)&gates, g_gates);
    cudaGetSymbolAddress((void**)&ht,    g_ht);
    cudaGetSymbolAddress((void**)&ud,    g_ud);
    cudaGetSymbolAddress((void**)&rx,    g_rx);

    const dim3 blk(256);

    // K1: gates = x @ Wxt + bias[:3H]
    sgemm_k<0><<<dim3(G3 / 128, MROWS / 128), blk>>>(
        x, 1024, weight, WLD, bias, gates, G3,
        nullptr, nullptr, nullptr, nullptr);

    // Persistent scan: 512 steps in ONE launch (2 grid barriers per step)
    scan_kernel<<<NBLK_SCAN, blk>>>(weight, state);

    // K3: gd = ht @ Whd + bias[3H:]  (overwrites gates buffer)
    sgemm_k<0><<<dim3(G3 / 128, MROWS / 128), blk>>>(
        ht, 1024, weight + (size_t)D_ * WLD + G3, WLD, bias + G3, gates, G3,
        nullptr, nullptr, nullptr, nullptr);

    // K4: g2 = sigmoid(gd[:, :2D] + x @ Wxd[:, :2D]) -> ud, rx
    sgemm_k<1><<<dim3(2048 / 128, MROWS / 128), blk>>>(
        x, 1024, weight + G3, WLD, nullptr, nullptr, 0,
        gates, x, ud, rx);

    // K5: h = x + ud * (tanh(gd[:, 2D:] + rx @ Wxd[:, 2D:]) - x)
    sgemm_k<2><<<dim3(1024 / 128, MROWS / 128), blk>>>(
        rx, 1024, weight + G3 + 2 * D_, WLD, nullptr, out, D_,
        gates, x, ud, nullptr);

    // final_ht
    copy_final<<<128, blk>>>(out + (size_t)MROWS * D_);
}

// round 7
// speedup vs baseline: 1.2377x; 1.2377x over previous
#include <cuda_runtime.h>
#include <math.h>

// ----------------------------------------------------------------------------
// GridGRU  (D = H = 1024, N = 32, T = 512)
//
// R7: big GEMMs (K1/K3/K4/K5, 309 GFLOP total) moved from fp32 SIMT (FFMA,
// ~17 TF/s effective) to TF32 tensor cores (mma.sync m16n8k8, fp32 accum).
// Scan stays exact fp32 (persistent kernel, unchanged from R5).
//
//   K1    gates = x @ Wxt + b[:3H]              (16384x1024 @ 1024x3072)
//   SCAN  one kernel, 128 CTAs, 512 steps, 2 grid barriers/step
//   K3    gd = ht @ Whd + b[3H:]                (reuses gates buffer)
//   K4    g2 = sigmoid(gd[:, :2D] + x @ Wxd[:, :2D]) -> ud, rx = rd*x  (fused)
//   K5    h  = x + ud * (tanh(gd[:,2D:] + rx @ Wxd[:,2D:]) - x)        (fused)
//   copy final_ht
// ----------------------------------------------------------------------------

#define D_    1024
#define H_    1024
#define NB    32
#define TT    512
#define MROWS (NB * TT)     // 16384
#define WLD   6144          // weight row stride (2048 x 6144)
#define G3    3072
#define NBLK_SCAN 128

// Scratch (device globals: allocation-free per harness rules)
__device__ float g_gates[(size_t)MROWS * G3];   // gates, then reused as gd
__device__ float g_ht[(size_t)MROWS * H_];      // ht sequence, (n, t, h) row-major
__device__ float g_u [NB * H_];                 // per-step u gate
__device__ float g_rh[NB * H_];                 // per-step r * h_prev
__device__ float g_ud[(size_t)MROWS * D_];      // decoder update gate
__device__ float g_rx[(size_t)MROWS * D_];      // rd * x

// ------------------------- software grid barrier ----------------------------
__device__ unsigned int g_bar_count = 0;
__device__ unsigned int g_bar_gen   = 0;

__device__ __forceinline__ void grid_barrier()
{
    __syncthreads();
    __threadfence();
    if (threadIdx.x == 0) {
        unsigned int gen = *(volatile unsigned int*)&g_bar_gen;
        unsigned int tk  = atomicAdd(&g_bar_count, 1u);
        if (tk == NBLK_SCAN - 1) {
            g_bar_count = 0;
            __threadfence();
            *(volatile unsigned int*)&g_bar_gen = gen + 1u;
        } else {
            while (*(volatile unsigned int*)&g_bar_gen == gen) { __nanosleep(64); }
        }
        __threadfence();
    }
    __syncthreads();
}

// ----------------------------------------------------------------------------
// Persistent scan kernel (unchanged from R5 — exact fp32).
// ----------------------------------------------------------------------------
__global__ void __launch_bounds__(256, 1)
scan_kernel(const float* __restrict__ weight, const float* __restrict__ state)
{
    __shared__ __align__(16) float region0[5248];   // tiles (A: 3136f, B: 5248f)
    __shared__ __align__(16) float region1[2112];   // epilogue staging

    const int tid = threadIdx.x;
    const int b   = blockIdx.x;
    const int n   = tid & 31;
    const int w   = tid >> 5;

    // phase A mapping
    const int gA  = tid >> 7;          // K-half 0/1
    const int lA  = tid & 127;
    const int wgA = w & 3;             // warp-in-group -> 4 cols
    float* hsA = region0;              // [2][32][33]
    float* wsA = region0 + 2 * 32 * 33;// [2][32][16]
    // phase B mapping
    const int gB  = tid >> 6;          // K-quarter 0..3
    const int lB  = tid & 63;
    const int wgB = w & 1;             // warp-in-group -> 4 cols
    float* hsB = region0;              // [4][32][33]
    float* wsB = region0 + 4 * 32 * 33;// [4][32][8]

    const int jbA = b << 4;            // 16 cols in [0,2048)
    const int jbB = b << 3;            // 8 cols in [0,1024)

    for (int t = 0; t < TT; ++t) {
        const float* hp; size_t hstr;
        if (t == 0) { hp = state; hstr = (size_t)H_; }
        else        { hp = g_ht + (size_t)(t - 1) * H_; hstr = (size_t)TT * H_; }

        // =============================== Phase A ===============================
        float a0 = 0.f, a1 = 0.f, a2 = 0.f, a3 = 0.f;
        {
            const int kbase = gA << 9;               // 0 or 512
#pragma unroll 1
            for (int c0 = 0; c0 < 16; ++c0) {
                const int k0 = kbase + (c0 << 5);
#pragma unroll
                for (int i = 0; i < 8; ++i) {        // stage h tile 32k x 32n
                    int idx = lA + (i << 7);
                    int nn = idx >> 5, kk = idx & 31;
                    hsA[(gA * 32 + kk) * 33 + nn] = hp[(size_t)nn * hstr + k0 + kk];
                }
#pragma unroll
                for (int i = 0; i < 4; ++i) {        // stage w tile 32k x 16c
                    int idx = lA + (i << 7);
                    int kk = idx >> 4, c = idx & 15;
                    wsA[(gA * 32 + kk) * 16 + c] =
                        weight[(size_t)(D_ + k0 + kk) * WLD + jbA + c];
                }
                __syncthreads();
#pragma unroll
                for (int kk = 0; kk < 32; ++kk) {
                    float hv = hsA[(gA * 32 + kk) * 33 + n];
                    const float4 w4 =
                        *(const float4*)&wsA[(gA * 32 + kk) * 16 + (wgA << 2)];
                    a0 = fmaf(hv, w4.x, a0);
                    a1 = fmaf(hv, w4.y, a1);
                    a2 = fmaf(hv, w4.z, a2);
                    a3 = fmaf(hv, w4.w, a3);
                }
                __syncthreads();
            }
        }
        {   // combine + epilogue
            float* paccA = region1;          // [16][33]
            float* gsm   = region1 + 528;    // [16][33]
            float* hpe   = region1 + 1056;   // [16][33]
            float* sout  = region1 + 1584;   // [16][33]
            if (gA == 1) {
                paccA[(wgA * 4 + 0) * 33 + n] = a0;
                paccA[(wgA * 4 + 1) * 33 + n] = a1;
                paccA[(wgA * 4 + 2) * 33 + n] = a2;
                paccA[(wgA * 4 + 3) * 33 + n] = a3;
            }
#pragma unroll
            for (int i = 0; i < 2; ++i) {    // stage gates (coalesced 64B rows)
                int idx = tid + (i << 8);
                int c = idx & 15, nn = idx >> 4;
                gsm[c * 33 + nn] =
                    g_gates[(size_t)nn * TT * G3 + (size_t)t * G3 + jbA + c];
            }
            if (b >= 64) {                   // stage h_prev for r-cols
#pragma unroll
                for (int i = 0; i < 2; ++i) {
                    int idx = tid + (i << 8);
                    int c = idx & 15, nn = idx >> 4;
                    hpe[c * 33 + nn] = hp[(size_t)nn * hstr + (jbA - H_) + c];
                }
            }
            __syncthreads();
            if (gA == 0) {
                float av[4] = {a0, a1, a2, a3};
#pragma unroll
                for (int c = 0; c < 4; ++c) {
                    int cc = wgA * 4 + c;
                    float z = av[c] + paccA[cc * 33 + n] + gsm[cc * 33 + n];
                    float s = 1.f / (1.f + expf(-z));
                    float o = (b < 64) ? s : s * hpe[cc * 33 + n];
                    sout[cc * 33 + n] = o;
                }
            }
            __syncthreads();
            {   // coalesced store of u / rh
                float* dst = (b < 64) ? g_u : g_rh;
                const int jb0 = (b < 64) ? jbA : (jbA - H_);
#pragma unroll
                for (int i = 0; i < 2; ++i) {
                    int idx = tid + (i << 8);
                    int c = idx & 15, nn = idx >> 4;
                    dst[nn * H_ + jb0 + c] = sout[c * 33 + nn];
                }
            }
        }
        grid_barrier();

        // =============================== Phase B ===============================
        float b0 = 0.f, b1 = 0.f, b2 = 0.f, b3 = 0.f;
        {
            const int kbase = gB << 8;               // 0,256,512,768
#pragma unroll 1
            for (int c0 = 0; c0 < 8; ++c0) {
                const int k0 = kbase + (c0 << 5);
#pragma unroll
                for (int i = 0; i < 16; ++i) {       // stage rh tile 32k x 32n
                    int idx = lB + (i << 6);
                    int nn = idx >> 5, kk = idx & 31;
                    hsB[(gB * 32 + kk) * 33 + nn] = g_rh[nn * H_ + k0 + kk];
                }
#pragma unroll
                for (int i = 0; i < 4; ++i) {        // stage w tile 32k x 8c
                    int idx = lB + (i << 6);
                    int kk = idx >> 3, c = idx & 7;
                    wsB[(gB * 32 + kk) * 8 + c] =
                        weight[(size_t)(D_ + k0 + kk) * WLD + 2 * H_ + jbB + c];
                }
                __syncthreads();
#pragma unroll
                for (int kk = 0; kk < 32; ++kk) {
                    float hv = hsB[(gB * 32 + kk) * 33 + n];
                    const float4 w4 =
                        *(const float4*)&wsB[(gB * 32 + kk) * 8 + (wgB << 2)];
                    b0 = fmaf(hv, w4.x, b0);
                    b1 = fmaf(hv, w4.y, b1);
                    b2 = fmaf(hv, w4.z, b2);
                    b3 = fmaf(hv, w4.w, b3);
                }
                __syncthreads();
            }
        }
        {   // combine + epilogue
            float* paccB = region1;          // [3][8][33] = 792
            float* gsm2  = region1 + 792;    // [8][33]
            float* hpb   = region1 + 1056;   // [8][33]
            float* ub    = region1 + 1320;   // [8][33]
            float* hout  = region1 + 1584;   // [8][33]
            if (gB > 0) {
                float* p = paccB + (gB - 1) * 264;
                p[(wgB * 4 + 0) * 33 + n] = b0;
                p[(wgB * 4 + 1) * 33 + n] = b1;
                p[(wgB * 4 + 2) * 33 + n] = b2;
                p[(wgB * 4 + 3) * 33 + n] = b3;
            }
            {   // stage gates / h_prev / u (coalesced 32B rows)
                int c = tid & 7, nn = tid >> 3;
                gsm2[c * 33 + nn] =
                    g_gates[(size_t)nn * TT * G3 + (size_t)t * G3 + 2 * H_ + jbB + c];
                hpb[c * 33 + nn] = hp[(size_t)nn * hstr + jbB + c];
                ub[c * 33 + nn]  = g_u[nn * H_ + jbB + c];
            }
            __syncthreads();
            if (gB == 0) {
                float bv[4] = {b0, b1, b2, b3};
#pragma unroll
                for (int c = 0; c < 4; ++c) {
                    int cc = wgB * 4 + c;
                    float z = bv[c] + paccB[cc * 33 + n] + paccB[264 + cc * 33 + n]
                            + paccB[528 + cc * 33 + n] + gsm2[cc * 33 + n];
                    float hc = tanhf(z);
                    float hv = hpb[cc * 33 + n];
                    float u  = ub[cc * 33 + n];
                    hout[cc * 33 + n] = fmaf(u, hc - hv, hv);
                }
            }
            __syncthreads();
            {   // coalesced store of h_t
                int c = tid & 7, nn = tid >> 3;
                g_ht[(size_t)nn * TT * H_ + (size_t)t * H_ + jbB + c] =
                    hout[c * 33 + nn];
            }
        }
        grid_barrier();
    }
}

// ----------------------------------------------------------------------------
// TF32 tensor-core GEMM: C(M x Ncols) = A(M x 1024) @ B(1024 x Ncols).
// 128x128x16 CTA tile, 256 threads = 8 warps (4m x 2n), warp tile 32x64,
// mma.sync.m16n8k8 tf32, fp32 accumulate. tf32 conversion at staging.
// Smem: As[m][k] stride 20 (conflict-free frag loads), Bs[k][n] stride 136.
// MODE 0: C = acc + bias[col]
// MODE 1: s = sigmoid(gd[m, col] + acc); col<D -> ud, else rx = s * x
// MODE 2: hcd = tanh(gd[m, 2D+col] + acc); C = x + ud*(hcd - x)
// ----------------------------------------------------------------------------
__device__ __forceinline__ unsigned f2tf(float f)
{
    unsigned u;
    asm("cvt.rna.tf32.f32 %0, %1;" : "=r"(u) : "f"(f));
    return u;
}

__device__ __forceinline__ void mma_tf32(float c[4], const unsigned a[4],
                                         unsigned b0, unsigned b1)
{
    asm volatile(
        "mma.sync.aligned.m16n8k8.row.col.f32.tf32.tf32.f32 "
        "{%0,%1,%2,%3}, {%4,%5,%6,%7}, {%8,%9}, {%0,%1,%2,%3};\n"
        : "+f"(c[0]), "+f"(c[1]), "+f"(c[2]), "+f"(c[3])
        : "r"(a[0]), "r"(a[1]), "r"(a[2]), "r"(a[3]), "r"(b0), "r"(b1));
}

#define AS_LD 20
#define BS_LD 136

template <int MODE>
__global__ void __launch_bounds__(256, 2)
tgemm_k(const float* __restrict__ A, int lda,
        const float* __restrict__ B, int ldb,
        const float* __restrict__ bias,
        float* __restrict__ C, int ldc,
        const float* __restrict__ gdp,
        const float* __restrict__ xp,
        float* __restrict__ udp,
        float* __restrict__ rxp)
{
    __shared__ __align__(16) unsigned As[128 * AS_LD];   // [m][k]
    __shared__ __align__(16) unsigned Bs[16 * BS_LD];    // [k][n]

    const int tid  = threadIdx.x;
    const int lane = tid & 31;
    const int warp = tid >> 5;
    const int gid  = lane >> 2;
    const int tg   = lane & 3;
    const int wm   = warp & 3;     // 0..3  (m)
    const int wn   = warp >> 2;    // 0..1  (n)

    const int rowBase = blockIdx.y << 7;
    const int colBase = blockIdx.x << 7;

    // staging assignments
    const int arow = tid >> 1;            // 0..127
    const int ak   = (tid & 1) << 3;      // 0 or 8
    const int bk   = tid >> 4;            // 0..15
    const int bn   = (tid & 15) << 3;     // 0..120

    const float* Ag = A + (size_t)(rowBase + arow) * lda + ak;
    const float* Bg = B + (size_t)bk * ldb + colBase + bn;

    float c[2][8][4];
#pragma unroll
    for (int mt = 0; mt < 2; ++mt)
#pragma unroll
        for (int nt = 0; nt < 8; ++nt)
#pragma unroll
            for (int e = 0; e < 4; ++e) c[mt][nt][e] = 0.f;

    float4 av0, av1, bv0, bv1;
    av0 = *(const float4*)(Ag);
    av1 = *(const float4*)(Ag + 4);
    bv0 = *(const float4*)(Bg);
    bv1 = *(const float4*)(Bg + 4);

    const int NIT = 1024 / 16;   // 64

#pragma unroll 1
    for (int kt = 0; kt < NIT; ++kt) {
        // stage current tile (tf32-convert once here)
        *(uint4*)&As[arow * AS_LD + ak] =
            make_uint4(f2tf(av0.x), f2tf(av0.y), f2tf(av0.z), f2tf(av0.w));
        *(uint4*)&As[arow * AS_LD + ak + 4] =
            make_uint4(f2tf(av1.x), f2tf(av1.y), f2tf(av1.z), f2tf(av1.w));
        *(uint4*)&Bs[bk * BS_LD + bn] =
            make_uint4(f2tf(bv0.x), f2tf(bv0.y), f2tf(bv0.z), f2tf(bv0.w));
        *(uint4*)&Bs[bk * BS_LD + bn + 4] =
            make_uint4(f2tf(bv1.x), f2tf(bv1.y), f2tf(bv1.z), f2tf(bv1.w));
        __syncthreads();

        // prefetch next tile under the mma work
        if (kt + 1 < NIT) {
            const float* Ap = Ag + (kt + 1) * 16;
            av0 = *(const float4*)(Ap);
            av1 = *(const float4*)(Ap + 4);
            const float* Bp = Bg + (size_t)(kt + 1) * 16 * ldb;
            bv0 = *(const float4*)(Bp);
            bv1 = *(const float4*)(Bp + 4);
        }

#pragma unroll
        for (int ks = 0; ks < 2; ++ks) {
            unsigned a[2][4];
#pragma unroll
            for (int mt = 0; mt < 2; ++mt) {
                const int r = (wm * 32 + mt * 16 + gid) * AS_LD + ks * 8 + tg;
                a[mt][0] = As[r];
                a[mt][1] = As[r + 8 * AS_LD];
                a[mt][2] = As[r + 4];
                a[mt][3] = As[r + 8 * AS_LD + 4];
            }
#pragma unroll
            for (int nt = 0; nt < 8; ++nt) {
                const int nidx = wn * 64 + nt * 8 + gid;
                const unsigned b0 = Bs[(ks * 8 + tg) * BS_LD + nidx];
                const unsigned b1 = Bs[(ks * 8 + tg + 4) * BS_LD + nidx];
                mma_tf32(c[0][nt], a[0], b0, b1);
                mma_tf32(c[1][nt], a[1], b0, b1);
            }
        }
        __syncthreads();
    }

    // epilogue
#pragma unroll
    for (int mt = 0; mt < 2; ++mt) {
#pragma unroll
        for (int nt = 0; nt < 8; ++nt) {
#pragma unroll
            for (int e = 0; e < 4; ++e) {
                const int m   = rowBase + wm * 32 + mt * 16 + gid + (e >> 1) * 8;
                const int col = colBase + wn * 64 + nt * 8 + tg * 2 + (e & 1);
                const float v = c[mt][nt][e];
                if (MODE == 0) {
                    C[(size_t)m * ldc + col] = v + bias[col];
                } else if (MODE == 1) {
                    float s = 1.f / (1.f + expf(-(gdp[(size_t)m * G3 + col] + v)));
                    if (col < D_) {
                        udp[(size_t)m * D_ + col] = s;
                    } else {
                        const int d = col - D_;
                        rxp[(size_t)m * D_ + d] = s * xp[(size_t)m * D_ + d];
                    }
                } else {  // MODE 2
                    float hcd = tanhf(gdp[(size_t)m * G3 + 2 * D_ + col] + v);
                    float xv  = xp[(size_t)m * D_ + col];
                    C[(size_t)m * D_ + col] =
                        fmaf(udp[(size_t)m * D_ + col], hcd - xv, xv);
                }
            }
        }
    }
}

// final_ht = ht[:, T-1, :]
__global__ void __launch_bounds__(256)
copy_final(float* __restrict__ out)
{
    int i = blockIdx.x * 256 + threadIdx.x;          // 0 .. 32767
    int n = i >> 10, h = i & 1023;
    out[i] = g_ht[(size_t)n * TT * H_ + (size_t)(TT - 1) * H_ + h];
}

// ----------------------------------------------------------------------------
extern "C" void kernel_launch(void* const* d_in, const int* in_sizes, int n_in,
                              void* d_out, int out_size)
{
    const float* x      = (const float*)d_in[0];   // (N, T, D)
    const float* state  = (const float*)d_in[1];   // (N, H)
    const float* weight = (const float*)d_in[2];   // (2048, 6144)
    const float* bias   = (const float*)d_in[3];   // (6144,)
    float*       out    = (float*)d_out;           // h (N,T,D) then final_ht (N,H)

    float *gates, *ht, *ud, *rx;
    cudaGetSymbolAddress((void**)&gates, g_gates);
    cudaGetSymbolAddress((void**)&ht,    g_ht);
    cudaGetSymbolAddress((void**)&ud,    g_ud);
    cudaGetSymbolAddress((void**)&rx,    g_rx);

    const dim3 blk(256);

    // K1: gates = x @ Wxt + bias[:3H]
    tgemm_k<0><<<dim3(G3 / 128, MROWS / 128), blk>>>(
        x, 1024, weight, WLD, bias, gates, G3,
        nullptr, nullptr, nullptr, nullptr);

    // Persistent scan: 512 steps in ONE launch (2 grid barriers per step)
    scan_kernel<<<NBLK_SCAN, blk>>>(weight, state);

    // K3: gd = ht @ Whd + bias[3H:]  (overwrites gates buffer)
    tgemm_k<0><<<dim3(G3 / 128, MROWS / 128), blk>>>(
        ht, 1024, weight + (size_t)D_ * WLD + G3, WLD, bias + G3, gates, G3,
        nullptr, nullptr, nullptr, nullptr);

    // K4: g2 = sigmoid(gd[:, :2D] + x @ Wxd[:, :2D]) -> ud, rx
    tgemm_k<1><<<dim3(2048 / 128, MROWS / 128), blk>>>(
        x, 1024, weight + G3, WLD, nullptr, nullptr, 0,
        gates, x, ud, rx);

    // K5: h = x + ud * (tanh(gd[:, 2D:] + rx @ Wxd[:, 2D:]) - x)
    tgemm_k<2><<<dim3(1024 / 128, MROWS / 128), blk>>>(
        rx, 1024, weight + G3 + 2 * D_, WLD, nullptr, out, D_,
        gates, x, ud, nullptr);

    // final_ht
    copy_final<<<128, blk>>>(out + (size_t)MROWS * D_);
}

// round 8
// speedup vs baseline: 1.6788x; 1.3564x over previous
#include <cuda_runtime.h>
#include <math.h>

// ----------------------------------------------------------------------------
// GridGRU  (D = H = 1024, N = 32, T = 512)
//
// R8: scan rewritten — weights smem-resident (96 KB/CTA, loaded once),
// h/rh streamed with cp.async double-buffering, packed fma.rn.f32x2 math.
// GEMMs (TF32 mma) unchanged from R7.
// ----------------------------------------------------------------------------

#define D_    1024
#define H_    1024
#define NB    32
#define TT    512
#define MROWS (NB * TT)     // 16384
#define WLD   6144          // weight row stride (2048 x 6144)
#define G3    3072
#define NBLK_SCAN 128

// Scratch (device globals: allocation-free per harness rules)
__device__ float g_gates[(size_t)MROWS * G3];   // gates, then reused as gd
__device__ float g_ht[(size_t)MROWS * H_];      // ht sequence, (n, t, h) row-major
__device__ float g_u [NB * H_];                 // per-step u gate
__device__ float g_rh[NB * H_];                 // per-step r * h_prev
__device__ float g_ud[(size_t)MROWS * D_];      // decoder update gate
__device__ float g_rx[(size_t)MROWS * D_];      // rd * x

// ------------------------- software grid barrier ----------------------------
__device__ unsigned int g_bar_count = 0;
__device__ unsigned int g_bar_gen   = 0;

__device__ __forceinline__ void grid_barrier()
{
    __syncthreads();
    __threadfence();
    if (threadIdx.x == 0) {
        unsigned int gen = *(volatile unsigned int*)&g_bar_gen;
        unsigned int tk  = atomicAdd(&g_bar_count, 1u);
        if (tk == NBLK_SCAN - 1) {
            g_bar_count = 0;
            __threadfence();
            *(volatile unsigned int*)&g_bar_gen = gen + 1u;
        } else {
            while (*(volatile unsigned int*)&g_bar_gen == gen) { __nanosleep(64); }
        }
        __threadfence();
    }
    __syncthreads();
}

// ------------------------- small asm helpers --------------------------------
__device__ __forceinline__ unsigned smem_u32(const void* p)
{
    return (unsigned)__cvta_generic_to_shared(p);
}
__device__ __forceinline__ void cp4(unsigned dst, const float* src)
{
    asm volatile("cp.async.ca.shared.global [%0], [%1], 4;" :: "r"(dst), "l"(src));
}
__device__ __forceinline__ void cp_commit()
{
    asm volatile("cp.async.commit_group;");
}
__device__ __forceinline__ void cp_wait0()
{
    asm volatile("cp.async.wait_group 0;");
}
// packed fp32x2 FMA: c += a * b  (element-wise on both halves)
__device__ __forceinline__ void ffma2(float2& c, float2 a, float2 b)
{
    asm volatile("fma.rn.f32x2 %0, %1, %2, %0;"
                 : "+l"(reinterpret_cast<unsigned long long&>(c))
                 : "l"(reinterpret_cast<unsigned long long&>(a)),
                   "l"(reinterpret_cast<unsigned long long&>(b)));
}

// ----------------------------------------------------------------------------
// Persistent scan kernel. 128 CTAs x 256 threads.
// smem layout (floats):
//   WA   [1024][16]          @ 0       (16384)  Whtg slice (16 cols)
//   WB   [1024][8]           @ 16384   (8192)   Whtc slice (8 cols)
//   TL   8 x 2112            @ 24576   (16896)  tile ring (A: 4 grp x 2 buf of
//                                               [64][33]; B: 8 grp x 2 buf of
//                                               [32][33])
//   PACC [4][16][33]/[8][8][33] @ 41472 (2112)  partial sums
//   GSM  [16][33]            @ 43584   (528)    gates staging
//   HPE  [16][33]            @ 44112   (528)    h_prev staging
//   UB   [8][33]             @ 44640   (528)    u staging (phase B)
// total 45168 floats = 180672 B
// ----------------------------------------------------------------------------
#define OFF_WB   16384
#define OFF_TL   24576
#define OFF_PACC 41472
#define OFF_GSM  43584
#define OFF_HPE  44112
#define OFF_UB   44640
#define SMEM_FLOATS 45168

extern __shared__ float smem[];

__global__ void __launch_bounds__(256, 1)
scan_kernel(const float* __restrict__ weight, const float* __restrict__ state)
{
    float* WA   = smem;
    float* WB   = smem + OFF_WB;
    float* TL   = smem + OFF_TL;
    float* PACC = smem + OFF_PACC;
    float* GSM  = smem + OFF_GSM;
    float* HPE  = smem + OFF_HPE;
    float* UB   = smem + OFF_UB;

    const int tid  = threadIdx.x;
    const int b    = blockIdx.x;
    const int lane = tid & 31;
    const int w    = tid >> 5;
    const int jbA  = b << 4;            // 16 cols in [0,2048)
    const int jbB  = b << 3;            // 8 cols in [0,1024)

    const int kgA = w >> 1;             // phase A K-group 0..3 (256 K each)
    const int chA = w & 1;              // phase A col-half (8 cols)
    const int kgB = w;                  // phase B K-group 0..7 (128 K each)

    // ---- load weight slices once (resident for all 512 steps) ----
#pragma unroll 4
    for (int j = 0; j < 64; ++j) {
        int idx = tid + (j << 8);
        int c = idx & 15, k = idx >> 4;
        WA[idx] = weight[(size_t)(D_ + k) * WLD + jbA + c];
    }
#pragma unroll 4
    for (int j = 0; j < 32; ++j) {
        int idx = tid + (j << 8);
        int c = idx & 7, k = idx >> 3;
        WB[idx] = weight[(size_t)(D_ + k) * WLD + 2 * H_ + jbB + c];
    }
    __syncthreads();

    for (int t = 0; t < TT; ++t) {
        const float* hp; size_t hstr;
        if (t == 0) { hp = state; hstr = (size_t)H_; }
        else        { hp = g_ht + (size_t)(t - 1) * H_; hstr = (size_t)TT * H_; }

        // =========================== Phase A ===========================
        // gg = sigmoid(gates_t[:, :2H] + h_prev @ Whtg); b<64 -> u, else rh
        {
            // epilogue staging (group E)
            int c = tid & 15, nn = tid >> 4;
            cp4(smem_u32(&GSM[c * 33 + nn]),
                g_gates + (size_t)nn * TT * G3 + (size_t)t * G3 + jbA + c);
            cp4(smem_u32(&GSM[c * 33 + nn + 16]),
                g_gates + (size_t)(nn + 16) * TT * G3 + (size_t)t * G3 + jbA + c);
            if (b >= 64) {
                cp4(smem_u32(&HPE[c * 33 + nn]),
                    hp + (size_t)nn * hstr + (jbA - H_) + c);
                cp4(smem_u32(&HPE[c * 33 + nn + 16]),
                    hp + (size_t)(nn + 16) * hstr + (jbA - H_) + c);
            }
            cp_commit();
        }
        // tile 0
#pragma unroll
        for (int g = 0; g < 4; ++g) {
            float* tb = TL + (g * 2) * 2112;
            const float* s0 = hp + (g << 8);
#pragma unroll
            for (int j = 0; j < 8; ++j) {
                int idx = tid + (j << 8);
                int k = idx & 63, nn = idx >> 6;
                cp4(smem_u32(&tb[k * 33 + nn]), s0 + (size_t)nn * hstr + k);
            }
        }
        cp_commit();

        float2 acc[4];
        acc[0] = acc[1] = acc[2] = acc[3] = make_float2(0.f, 0.f);

#pragma unroll 1
        for (int i = 0; i < 4; ++i) {
            cp_wait0();
            __syncthreads();
            if (i + 1 < 4) {
#pragma unroll
                for (int g = 0; g < 4; ++g) {
                    float* tb = TL + (g * 2 + ((i + 1) & 1)) * 2112;
                    const float* s0 = hp + (g << 8) + ((i + 1) << 6);
#pragma unroll
                    for (int j = 0; j < 8; ++j) {
                        int idx = tid + (j << 8);
                        int k = idx & 63, nn = idx >> 6;
                        cp4(smem_u32(&tb[k * 33 + nn]), s0 + (size_t)nn * hstr + k);
                    }
                }
                cp_commit();
            }
            const float* buf = TL + (kgA * 2 + (i & 1)) * 2112;
            const float* wb  = WA + ((kgA << 8) + (i << 6)) * 16 + (chA << 3);
#pragma unroll 16
            for (int kk = 0; kk < 64; ++kk) {
                float  hv  = buf[kk * 33 + lane];
                float2 hv2 = make_float2(hv, hv);
                const float4 w0 = *(const float4*)(wb + kk * 16);
                const float4 w1 = *(const float4*)(wb + kk * 16 + 4);
                ffma2(acc[0], hv2, make_float2(w0.x, w0.y));
                ffma2(acc[1], hv2, make_float2(w0.z, w0.w));
                ffma2(acc[2], hv2, make_float2(w1.x, w1.y));
                ffma2(acc[3], hv2, make_float2(w1.z, w1.w));
            }
        }
        // store partials
#pragma unroll
        for (int q = 0; q < 4; ++q) {
            PACC[kgA * 528 + ((chA << 3) + 2 * q)     * 33 + lane] = acc[q].x;
            PACC[kgA * 528 + ((chA << 3) + 2 * q + 1) * 33 + lane] = acc[q].y;
        }
        __syncthreads();
        // distributed epilogue + direct coalesced store
        {
            float* dst = (b < 64) ? g_u : g_rh;
            const int jb0 = (b < 64) ? jbA : (jbA - H_);
#pragma unroll
            for (int s2 = 0; s2 < 2; ++s2) {
                int idx = tid + (s2 << 8);
                int c = idx & 15, nn = idx >> 4;
                float z = PACC[c * 33 + nn] + PACC[528 + c * 33 + nn]
                        + PACC[1056 + c * 33 + nn] + PACC[1584 + c * 33 + nn]
                        + GSM[c * 33 + nn];
                float s = 1.f / (1.f + expf(-z));
                float o = (b < 64) ? s : s * HPE[c * 33 + nn];
                dst[nn * H_ + jb0 + c] = o;
            }
        }
        grid_barrier();

        // =========================== Phase B ===========================
        // hc = tanh(gates_t[:, 2H:] + rh @ Whtc); h_t = h + u*(hc - h)
        {
            int c = tid & 7, nn = tid >> 3;
            cp4(smem_u32(&GSM[c * 33 + nn]),
                g_gates + (size_t)nn * TT * G3 + (size_t)t * G3 + 2 * H_ + jbB + c);
            cp4(smem_u32(&HPE[c * 33 + nn]), hp + (size_t)nn * hstr + jbB + c);
            cp4(smem_u32(&UB[c * 33 + nn]),  g_u + nn * H_ + jbB + c);
            cp_commit();
        }
#pragma unroll
        for (int g = 0; g < 8; ++g) {
            float* tb = TL + (g * 2) * 1056;
            const float* s0 = g_rh + (g << 7);
#pragma unroll
            for (int j = 0; j < 4; ++j) {
                int idx = tid + (j << 8);
                int k = idx & 31, nn = idx >> 5;
                cp4(smem_u32(&tb[k * 33 + nn]), s0 + nn * H_ + k);
            }
        }
        cp_commit();

        float2 accB[4];
        accB[0] = accB[1] = accB[2] = accB[3] = make_float2(0.f, 0.f);

#pragma unroll 1
        for (int i = 0; i < 4; ++i) {
            cp_wait0();
            __syncthreads();
            if (i + 1 < 4) {
#pragma unroll
                for (int g = 0; g < 8; ++g) {
                    float* tb = TL + (g * 2 + ((i + 1) & 1)) * 1056;
                    const float* s0 = g_rh + (g << 7) + ((i + 1) << 5);
#pragma unroll
                    for (int j = 0; j < 4; ++j) {
                        int idx = tid + (j << 8);
                        int k = idx & 31, nn = idx >> 5;
                        cp4(smem_u32(&tb[k * 33 + nn]), s0 + nn * H_ + k);
                    }
                }
                cp_commit();
            }
            const float* buf = TL + (kgB * 2 + (i & 1)) * 1056;
            const float* wb  = WB + ((kgB << 7) + (i << 5)) * 8;
#pragma unroll 16
            for (int kk = 0; kk < 32; ++kk) {
                float  hv  = buf[kk * 33 + lane];
                float2 hv2 = make_float2(hv, hv);
                const float4 w0 = *(const float4*)(wb + kk * 8);
                const float4 w1 = *(const float4*)(wb + kk * 8 + 4);
                ffma2(accB[0], hv2, make_float2(w0.x, w0.y));
                ffma2(accB[1], hv2, make_float2(w0.z, w0.w));
                ffma2(accB[2], hv2, make_float2(w1.x, w1.y));
                ffma2(accB[3], hv2, make_float2(w1.z, w1.w));
            }
        }
#pragma unroll
        for (int q = 0; q < 4; ++q) {
            PACC[kgB * 264 + (2 * q)     * 33 + lane] = accB[q].x;
            PACC[kgB * 264 + (2 * q + 1) * 33 + lane] = accB[q].y;
        }
        __syncthreads();
        {
            int c = tid & 7, nn = tid >> 3;
            float z = GSM[c * 33 + nn];
#pragma unroll
            for (int g = 0; g < 8; ++g) z += PACC[g * 264 + c * 33 + nn];
            float hc = tanhf(z);
            float hv = HPE[c * 33 + nn];
            float u  = UB[c * 33 + nn];
            g_ht[(size_t)nn * TT * H_ + (size_t)t * H_ + jbB + c] =
                fmaf(u, hc - hv, hv);
        }
        grid_barrier();
    }
}

// ----------------------------------------------------------------------------
// TF32 tensor-core GEMM (unchanged from R7).
// ----------------------------------------------------------------------------
__device__ __forceinline__ unsigned f2tf(float f)
{
    unsigned u;
    asm("cvt.rna.tf32.f32 %0, %1;" : "=r"(u) : "f"(f));
    return u;
}

__device__ __forceinline__ void mma_tf32(float c[4], const unsigned a[4],
                                         unsigned b0, unsigned b1)
{
    asm volatile(
        "mma.sync.aligned.m16n8k8.row.col.f32.tf32.tf32.f32 "
        "{%0,%1,%2,%3}, {%4,%5,%6,%7}, {%8,%9}, {%0,%1,%2,%3};\n"
        : "+f"(c[0]), "+f"(c[1]), "+f"(c[2]), "+f"(c[3])
        : "r"(a[0]), "r"(a[1]), "r"(a[2]), "r"(a[3]), "r"(b0), "r"(b1));
}

#define AS_LD 20
#define BS_LD 136

template <int MODE>
__global__ void __launch_bounds__(256, 2)
tgemm_k(const float* __restrict__ A, int lda,
        const float* __restrict__ B, int ldb,
        const float* __restrict__ bias,
        float* __restrict__ C, int ldc,
        const float* __restrict__ gdp,
        const float* __restrict__ xp,
        float* __restrict__ udp,
        float* __restrict__ rxp)
{
    __shared__ __align__(16) unsigned As[128 * AS_LD];   // [m][k]
    __shared__ __align__(16) unsigned Bs[16 * BS_LD];    // [k][n]

    const int tid  = threadIdx.x;
    const int lane = tid & 31;
    const int warp = tid >> 5;
    const int gid  = lane >> 2;
    const int tg   = lane & 3;
    const int wm   = warp & 3;     // 0..3  (m)
    const int wn   = warp >> 2;    // 0..1  (n)

    const int rowBase = blockIdx.y << 7;
    const int colBase = blockIdx.x << 7;

    const int arow = tid >> 1;            // 0..127
    const int ak   = (tid & 1) << 3;      // 0 or 8
    const int bk   = tid >> 4;            // 0..15
    const int bn   = (tid & 15) << 3;     // 0..120

    const float* Ag = A + (size_t)(rowBase + arow) * lda + ak;
    const float* Bg = B + (size_t)bk * ldb + colBase + bn;

    float c[2][8][4];
#pragma unroll
    for (int mt = 0; mt < 2; ++mt)
#pragma unroll
        for (int nt = 0; nt < 8; ++nt)
#pragma unroll
            for (int e = 0; e < 4; ++e) c[mt][nt][e] = 0.f;

    float4 av0, av1, bv0, bv1;
    av0 = *(const float4*)(Ag);
    av1 = *(const float4*)(Ag + 4);
    bv0 = *(const float4*)(Bg);
    bv1 = *(const float4*)(Bg + 4);

    const int NIT = 1024 / 16;   // 64

#pragma unroll 1
    for (int kt = 0; kt < NIT; ++kt) {
        *(uint4*)&As[arow * AS_LD + ak] =
            make_uint4(f2tf(av0.x), f2tf(av0.y), f2tf(av0.z), f2tf(av0.w));
        *(uint4*)&As[arow * AS_LD + ak + 4] =
            make_uint4(f2tf(av1.x), f2tf(av1.y), f2tf(av1.z), f2tf(av1.w));
        *(uint4*)&Bs[bk * BS_LD + bn] =
            make_uint4(f2tf(bv0.x), f2tf(bv0.y), f2tf(bv0.z), f2tf(bv0.w));
        *(uint4*)&Bs[bk * BS_LD + bn + 4] =
            make_uint4(f2tf(bv1.x), f2tf(bv1.y), f2tf(bv1.z), f2tf(bv1.w));
        __syncthreads();

        if (kt + 1 < NIT) {
            const float* Ap = Ag + (kt + 1) * 16;
            av0 = *(const float4*)(Ap);
            av1 = *(const float4*)(Ap + 4);
            const float* Bp = Bg + (size_t)(kt + 1) * 16 * ldb;
            bv0 = *(const float4*)(Bp);
            bv1 = *(const float4*)(Bp + 4);
        }

#pragma unroll
        for (int ks = 0; ks < 2; ++ks) {
            unsigned a[2][4];
#pragma unroll
            for (int mt = 0; mt < 2; ++mt) {
                const int r = (wm * 32 + mt * 16 + gid) * AS_LD + ks * 8 + tg;
                a[mt][0] = As[r];
                a[mt][1] = As[r + 8 * AS_LD];
                a[mt][2] = As[r + 4];
                a[mt][3] = As[r + 8 * AS_LD + 4];
            }
#pragma unroll
            for (int nt = 0; nt < 8; ++nt) {
                const int nidx = wn * 64 + nt * 8 + gid;
                const unsigned b0 = Bs[(ks * 8 + tg) * BS_LD + nidx];
                const unsigned b1 = Bs[(ks * 8 + tg + 4) * BS_LD + nidx];
                mma_tf32(c[0][nt], a[0], b0, b1);
                mma_tf32(c[1][nt], a[1], b0, b1);
            }
        }
        __syncthreads();
    }

#pragma unroll
    for (int mt = 0; mt < 2; ++mt) {
#pragma unroll
        for (int nt = 0; nt < 8; ++nt) {
#pragma unroll
            for (int e = 0; e < 4; ++e) {
                const int m   = rowBase + wm * 32 + mt * 16 + gid + (e >> 1) * 8;
                const int col = colBase + wn * 64 + nt * 8 + tg * 2 + (e & 1);
                const float v = c[mt][nt][e];
                if (MODE == 0) {
                    C[(size_t)m * ldc + col] = v + bias[col];
                } else if (MODE == 1) {
                    float s = 1.f / (1.f + expf(-(gdp[(size_t)m * G3 + col] + v)));
                    if (col < D_) {
                        udp[(size_t)m * D_ + col] = s;
                    } else {
                        const int d = col - D_;
                        rxp[(size_t)m * D_ + d] = s * xp[(size_t)m * D_ + d];
                    }
                } else {  // MODE 2
                    float hcd = tanhf(gdp[(size_t)m * G3 + 2 * D_ + col] + v);
                    float xv  = xp[(size_t)m * D_ + col];
                    C[(size_t)m * D_ + col] =
                        fmaf(udp[(size_t)m * D_ + col], hcd - xv, xv);
                }
            }
        }
    }
}

// final_ht = ht[:, T-1, :]
__global__ void __launch_bounds__(256)
copy_final(float* __restrict__ out)
{
    int i = blockIdx.x * 256 + threadIdx.x;          // 0 .. 32767
    int n = i >> 10, h = i & 1023;
    out[i] = g_ht[(size_t)n * TT * H_ + (size_t)(TT - 1) * H_ + h];
}

// ----------------------------------------------------------------------------
extern "C" void kernel_launch(void* const* d_in, const int* in_sizes, int n_in,
                              void* d_out, int out_size)
{
    const float* x      = (const float*)d_in[0];   // (N, T, D)
    const float* state  = (const float*)d_in[1];   // (N, H)
    const float* weight = (const float*)d_in[2];   // (2048, 6144)
    const float* bias   = (const float*)d_in[3];   // (6144,)
    float*       out    = (float*)d_out;           // h (N,T,D) then final_ht (N,H)

    float *gates, *ht, *ud, *rx;
    cudaGetSymbolAddress((void**)&gates, g_gates);
    cudaGetSymbolAddress((void**)&ht,    g_ht);
    cudaGetSymbolAddress((void**)&ud,    g_ud);
    cudaGetSymbolAddress((void**)&rx,    g_rx);

    const dim3 blk(256);
    const int scan_smem = SMEM_FLOATS * 4;   // 180672 B

    cudaFuncSetAttribute(scan_kernel,
                         cudaFuncAttributeMaxDynamicSharedMemorySize, scan_smem);

    // K1: gates = x @ Wxt + bias[:3H]
    tgemm_k<0><<<dim3(G3 / 128, MROWS / 128), blk>>>(
        x, 1024, weight, WLD, bias, gates, G3,
        nullptr, nullptr, nullptr, nullptr);

    // Persistent scan: 512 steps in ONE launch (2 grid barriers per step)
    scan_kernel<<<NBLK_SCAN, blk, scan_smem>>>(weight, state);

    // K3: gd = ht @ Whd + bias[3H:]  (overwrites gates buffer)
    tgemm_k<0><<<dim3(G3 / 128, MROWS / 128), blk>>>(
        ht, 1024, weight + (size_t)D_ * WLD + G3, WLD, bias + G3, gates, G3,
        nullptr, nullptr, nullptr, nullptr);

    // K4: g2 = sigmoid(gd[:, :2D] + x @ Wxd[:, :2D]) -> ud, rx
    tgemm_k<1><<<dim3(2048 / 128, MROWS / 128), blk>>>(
        x, 1024, weight + G3, WLD, nullptr, nullptr, 0,
        gates, x, ud, rx);

    // K5: h = x + ud * (tanh(gd[:, 2D:] + rx @ Wxd[:, 2D:]) - x)
    tgemm_k<2><<<dim3(1024 / 128, MROWS / 128), blk>>>(
        rx, 1024, weight + G3 + 2 * D_, WLD, nullptr, out, D_,
        gates, x, ud, nullptr);

    // final_ht
    copy_final<<<128, blk>>>(out + (size_t)MROWS * D_);
}

// round 9
// speedup vs baseline: 1.9525x; 1.1630x over previous
#include <cuda_runtime.h>
#include <math.h>

// ----------------------------------------------------------------------------
// GridGRU  (D = H = 1024, N = 32, T = 512)
//
// R9: scan rewritten again —
//   * per-warp private double-buffered tiles (no syncthreads in compute loop)
//   * 16B cp.async.cg staging, [n][k] tile layout (stride 36, LDS.128 reads)
//   * each warp: 1/8 of K, ALL columns (no duplicated h reads)
//   * 8-way K-partials combined in padded smem (stride 34, conflict-free)
// GEMMs (TF32 mma) unchanged from R7/R8.
// ----------------------------------------------------------------------------

#define D_    1024
#define H_    1024
#define NB    32
#define TT    512
#define MROWS (NB * TT)     // 16384
#define WLD   6144          // weight row stride (2048 x 6144)
#define G3    3072
#define NBLK_SCAN 128

// Scratch (device globals: allocation-free per harness rules)
__device__ float g_gates[(size_t)MROWS * G3];   // gates, then reused as gd
__device__ float g_ht[(size_t)MROWS * H_];      // ht sequence, (n, t, h) row-major
__device__ float g_u [NB * H_];                 // per-step u gate
__device__ float g_rh[NB * H_];                 // per-step r * h_prev
__device__ float g_ud[(size_t)MROWS * D_];      // decoder update gate
__device__ float g_rx[(size_t)MROWS * D_];      // rd * x

// ------------------------- software grid barrier ----------------------------
__device__ unsigned int g_bar_count = 0;
__device__ unsigned int g_bar_gen   = 0;

__device__ __forceinline__ void grid_barrier()
{
    __syncthreads();
    __threadfence();
    if (threadIdx.x == 0) {
        unsigned int gen = *(volatile unsigned int*)&g_bar_gen;
        unsigned int tk  = atomicAdd(&g_bar_count, 1u);
        if (tk == NBLK_SCAN - 1) {
            g_bar_count = 0;
            __threadfence();
            *(volatile unsigned int*)&g_bar_gen = gen + 1u;
        } else {
            while (*(volatile unsigned int*)&g_bar_gen == gen) { __nanosleep(32); }
        }
        __threadfence();
    }
    __syncthreads();
}

// ------------------------- small asm helpers --------------------------------
__device__ __forceinline__ unsigned smem_u32(const void* p)
{
    return (unsigned)__cvta_generic_to_shared(p);
}
__device__ __forceinline__ void cp16(unsigned dst, const float* src)
{
    asm volatile("cp.async.cg.shared.global [%0], [%1], 16;" :: "r"(dst), "l"(src));
}
__device__ __forceinline__ void cp_commit()
{
    asm volatile("cp.async.commit_group;");
}
__device__ __forceinline__ void cp_wait0()
{
    asm volatile("cp.async.wait_group 0;");
}
// packed fp32x2 FMA: c += a * b  (element-wise on both halves)
__device__ __forceinline__ void ffma2(float2& c, float2 a, float2 b)
{
    asm volatile("fma.rn.f32x2 %0, %1, %2, %0;"
                 : "+l"(reinterpret_cast<unsigned long long&>(c))
                 : "l"(reinterpret_cast<unsigned long long&>(a)),
                   "l"(reinterpret_cast<unsigned long long&>(b)));
}

// ----------------------------------------------------------------------------
// smem layout (floats):
//   WA   [1024][16]   @ 0       (16384)  Whtg slice, W[k][c]
//   WB   [1024][8]    @ 16384   (8192)   Whtc slice
//   TILE 8w x 2buf x [32][36]  @ 24576 (18432) per-warp h/rh tiles
//   PACC [8][16][34]  @ 43008   (4352)   K-partials (B uses [8][8][34])
//   GSM  [32][20]     @ 47360   (640)    A gates staging
//   HPE  [32][20]     @ 48000   (640)    A h_prev staging (r cols)
//   GSB  [32][12]     @ 48640   (384)    B gates staging
//   HPB  [32][12]     @ 49024   (384)    B h_prev staging
//   UBB  [32][12]     @ 49408   (384)    B u staging
// total 49792 floats = 199168 B
// ----------------------------------------------------------------------------
#define OFF_WB   16384
#define OFF_TILE 24576
#define OFF_PACC 43008
#define OFF_GSM  47360
#define OFF_HPE  48000
#define OFF_GSB  48640
#define OFF_HPB  49024
#define OFF_UBB  49408
#define SMEM_FLOATS 49792

extern __shared__ float smem[];

__global__ void __launch_bounds__(256, 1)
scan_kernel(const float* __restrict__ weight, const float* __restrict__ state)
{
    float* WA   = smem;
    float* WB   = smem + OFF_WB;
    float* PACC = smem + OFF_PACC;
    float* GSM  = smem + OFF_GSM;
    float* HPE  = smem + OFF_HPE;
    float* GSB  = smem + OFF_GSB;
    float* HPB  = smem + OFF_HPB;
    float* UBB  = smem + OFF_UBB;

    const int tid  = threadIdx.x;
    const int b    = blockIdx.x;
    const int lane = tid & 31;
    const int w    = tid >> 5;
    const int jbA  = b << 4;            // 16 cols in [0,2048)
    const int jbB  = b << 3;            // 8 cols in [0,1024)

    // per-warp tile buffers
    float* tile0 = smem + OFF_TILE + w * 2304;
    float* tile1 = tile0 + 1152;
    const unsigned t0u = smem_u32(tile0);
    const unsigned t1u = smem_u32(tile1);
    // tile-load lane mapping: lane -> (row group, 16B chunk)
    const int tl_n    = lane >> 3;           // 0..3
    const int tl_koff = (lane & 7) << 2;     // 0,4,...,28

    // ---- load weight slices once (resident for all 512 steps) ----
#pragma unroll 4
    for (int j = 0; j < 64; ++j) {
        int idx = tid + (j << 8);
        int c = idx & 15, k = idx >> 4;
        WA[idx] = weight[(size_t)(D_ + k) * WLD + jbA + c];
    }
#pragma unroll 4
    for (int j = 0; j < 32; ++j) {
        int idx = tid + (j << 8);
        int c = idx & 7, k = idx >> 3;
        WB[idx] = weight[(size_t)(D_ + k) * WLD + 2 * H_ + jbB + c];
    }
    __syncthreads();

    for (int t = 0; t < TT; ++t) {
        const float* hp; size_t hstr;
        if (t == 0) { hp = state; hstr = (size_t)H_; }
        else        { hp = g_ht + (size_t)(t - 1) * H_; hstr = (size_t)TT * H_; }

        // =========================== Phase A ===========================
        // gg = sigmoid(gates_t[:, :2H] + h_prev @ Whtg); b<64 -> u, else rh
        // epilogue staging: threads 0-127 -> GSM, threads 128-255 -> HPE
        if (tid < 128) {
            int n = tid >> 2, coff = (tid & 3) << 2;
            cp16(smem_u32(&GSM[n * 20 + coff]),
                 g_gates + (size_t)n * TT * G3 + (size_t)t * G3 + jbA + coff);
        } else if (b >= 64) {
            int tt2 = tid - 128;
            int n = tt2 >> 2, coff = (tt2 & 3) << 2;
            cp16(smem_u32(&HPE[n * 20 + coff]),
                 hp + (size_t)n * hstr + (jbA - H_) + coff);
        }
        // tile 0 for this warp (k range [w*128, w*128+32))
        {
            const int k0 = w << 7;
#pragma unroll
            for (int j = 0; j < 8; ++j) {
                int n = (j << 2) + tl_n;
                cp16(t0u + (unsigned)((n * 36 + tl_koff) << 2),
                     hp + (size_t)n * hstr + k0 + tl_koff);
            }
        }
        cp_commit();

        float2 acc[8];
#pragma unroll
        for (int q = 0; q < 8; ++q) acc[q] = make_float2(0.f, 0.f);

#pragma unroll
        for (int i = 0; i < 4; ++i) {
            cp_wait0();
            if (i < 3) {   // prefetch next chunk into other buffer
                const int k0 = (w << 7) + ((i + 1) << 5);
                const unsigned dst = (i & 1) ? t0u : t1u;
#pragma unroll
                for (int j = 0; j < 8; ++j) {
                    int n = (j << 2) + tl_n;
                    cp16(dst + (unsigned)((n * 36 + tl_koff) << 2),
                         hp + (size_t)n * hstr + k0 + tl_koff);
                }
                cp_commit();
            }
            const float* tb = (i & 1) ? tile1 : tile0;
            const int krow0 = (w << 7) + (i << 5);
#pragma unroll
            for (int kk4 = 0; kk4 < 8; ++kk4) {
                const float4 h4 = *(const float4*)&tb[lane * 36 + (kk4 << 2)];
                const float hv[4] = {h4.x, h4.y, h4.z, h4.w};
#pragma unroll
                for (int e = 0; e < 4; ++e) {
                    const float* wr = WA + (krow0 + (kk4 << 2) + e) * 16;
                    const float4 w0 = *(const float4*)(wr);
                    const float4 w1 = *(const float4*)(wr + 4);
                    const float4 w2 = *(const float4*)(wr + 8);
                    const float4 w3 = *(const float4*)(wr + 12);
                    float2 hv2 = make_float2(hv[e], hv[e]);
                    ffma2(acc[0], hv2, make_float2(w0.x, w0.y));
                    ffma2(acc[1], hv2, make_float2(w0.z, w0.w));
                    ffma2(acc[2], hv2, make_float2(w1.x, w1.y));
                    ffma2(acc[3], hv2, make_float2(w1.z, w1.w));
                    ffma2(acc[4], hv2, make_float2(w2.x, w2.y));
                    ffma2(acc[5], hv2, make_float2(w2.z, w2.w));
                    ffma2(acc[6], hv2, make_float2(w3.x, w3.y));
                    ffma2(acc[7], hv2, make_float2(w3.z, w3.w));
                }
            }
        }
        // store K-partials
#pragma unroll
        for (int q = 0; q < 8; ++q) {
            PACC[w * 544 + ((q << 1))     * 34 + lane] = acc[q].x;
            PACC[w * 544 + ((q << 1) + 1) * 34 + lane] = acc[q].y;
        }
        __syncthreads();
        // distributed epilogue + coalesced store of u / rh
        {
            float* dst = (b < 64) ? g_u : g_rh;
            const int jb0 = (b < 64) ? jbA : (jbA - H_);
#pragma unroll
            for (int s2 = 0; s2 < 2; ++s2) {
                int idx = tid + (s2 << 8);
                int c = idx & 15, n = idx >> 4;
                float z = GSM[n * 20 + c];
#pragma unroll
                for (int g = 0; g < 8; ++g) z += PACC[g * 544 + c * 34 + n];
                float s = 1.f / (1.f + expf(-z));
                float o = (b < 64) ? s : s * HPE[n * 20 + c];
                dst[n * H_ + jb0 + c] = o;
            }
        }
        // pre-barrier staging for phase B (gates + h_prev: both already valid)
        if (tid < 64) {
            int n = tid >> 1, coff = (tid & 1) << 2;
            cp16(smem_u32(&GSB[n * 12 + coff]),
                 g_gates + (size_t)n * TT * G3 + (size_t)t * G3 + 2 * H_ + jbB + coff);
        } else if (tid < 128) {
            int tt2 = tid - 64;
            int n = tt2 >> 1, coff = (tt2 & 1) << 2;
            cp16(smem_u32(&HPB[n * 12 + coff]),
                 hp + (size_t)n * hstr + jbB + coff);
        }
        cp_commit();
        grid_barrier();

        // =========================== Phase B ===========================
        // hc = tanh(gates_t[:, 2H:] + rh @ Whtc); h_t = h + u*(hc - h)
        if (tid < 64) {
            int n = tid >> 1, coff = (tid & 1) << 2;
            cp16(smem_u32(&UBB[n * 12 + coff]), g_u + n * H_ + jbB + coff);
        }
        {
            const int k0 = w << 7;
#pragma unroll
            for (int j = 0; j < 8; ++j) {
                int n = (j << 2) + tl_n;
                cp16(t0u + (unsigned)((n * 36 + tl_koff) << 2),
                     g_rh + n * H_ + k0 + tl_koff);
            }
        }
        cp_commit();

        float2 accB[4];
#pragma unroll
        for (int q = 0; q < 4; ++q) accB[q] = make_float2(0.f, 0.f);

#pragma unroll
        for (int i = 0; i < 4; ++i) {
            cp_wait0();
            if (i < 3) {
                const int k0 = (w << 7) + ((i + 1) << 5);
                const unsigned dst = (i & 1) ? t0u : t1u;
#pragma unroll
                for (int j = 0; j < 8; ++j) {
                    int n = (j << 2) + tl_n;
                    cp16(dst + (unsigned)((n * 36 + tl_koff) << 2),
                         g_rh + n * H_ + k0 + tl_koff);
                }
                cp_commit();
            }
            const float* tb = (i & 1) ? tile1 : tile0;
            const int krow0 = (w << 7) + (i << 5);
#pragma unroll
            for (int kk4 = 0; kk4 < 8; ++kk4) {
                const float4 h4 = *(const float4*)&tb[lane * 36 + (kk4 << 2)];
                const float hv[4] = {h4.x, h4.y, h4.z, h4.w};
#pragma unroll
                for (int e = 0; e < 4; ++e) {
                    const float* wr = WB + (krow0 + (kk4 << 2) + e) * 8;
                    const float4 w0 = *(const float4*)(wr);
                    const float4 w1 = *(const float4*)(wr + 4);
                    float2 hv2 = make_float2(hv[e], hv[e]);
                    ffma2(accB[0], hv2, make_float2(w0.x, w0.y));
                    ffma2(accB[1], hv2, make_float2(w0.z, w0.w));
                    ffma2(accB[2], hv2, make_float2(w1.x, w1.y));
                    ffma2(accB[3], hv2, make_float2(w1.z, w1.w));
                }
            }
        }
#pragma unroll
        for (int q = 0; q < 4; ++q) {
            PACC[w * 544 + ((q << 1))     * 34 + lane] = accB[q].x;
            PACC[w * 544 + ((q << 1) + 1) * 34 + lane] = accB[q].y;
        }
        __syncthreads();
        {
            int c = tid & 7, n = tid >> 3;
            float z = GSB[n * 12 + c];
#pragma unroll
            for (int g = 0; g < 8; ++g) z += PACC[g * 544 + c * 34 + n];
            float hc = tanhf(z);
            float hv = HPB[n * 12 + c];
            float u  = UBB[n * 12 + c];
            g_ht[(size_t)n * TT * H_ + (size_t)t * H_ + jbB + c] =
                fmaf(u, hc - hv, hv);
        }
        grid_barrier();
    }
}

// ----------------------------------------------------------------------------
// TF32 tensor-core GEMM (unchanged from R7).
// ----------------------------------------------------------------------------
__device__ __forceinline__ unsigned f2tf(float f)
{
    unsigned u;
    asm("cvt.rna.tf32.f32 %0, %1;" : "=r"(u) : "f"(f));
    return u;
}

__device__ __forceinline__ void mma_tf32(float c[4], const unsigned a[4],
                                         unsigned b0, unsigned b1)
{
    asm volatile(
        "mma.sync.aligned.m16n8k8.row.col.f32.tf32.tf32.f32 "
        "{%0,%1,%2,%3}, {%4,%5,%6,%7}, {%8,%9}, {%0,%1,%2,%3};\n"
        : "+f"(c[0]), "+f"(c[1]), "+f"(c[2]), "+f"(c[3])
        : "r"(a[0]), "r"(a[1]), "r"(a[2]), "r"(a[3]), "r"(b0), "r"(b1));
}

#define AS_LD 20
#define BS_LD 136

template <int MODE>
__global__ void __launch_bounds__(256, 2)
tgemm_k(const float* __restrict__ A, int lda,
        const float* __restrict__ B, int ldb,
        const float* __restrict__ bias,
        float* __restrict__ C, int ldc,
        const float* __restrict__ gdp,
        const float* __restrict__ xp,
        float* __restrict__ udp,
        float* __restrict__ rxp)
{
    __shared__ __align__(16) unsigned As[128 * AS_LD];   // [m][k]
    __shared__ __align__(16) unsigned Bs[16 * BS_LD];    // [k][n]

    const int tid  = threadIdx.x;
    const int lane = tid & 31;
    const int warp = tid >> 5;
    const int gid  = lane >> 2;
    const int tg   = lane & 3;
    const int wm   = warp & 3;     // 0..3  (m)
    const int wn   = warp >> 2;    // 0..1  (n)

    const int rowBase = blockIdx.y << 7;
    const int colBase = blockIdx.x << 7;

    const int arow = tid >> 1;            // 0..127
    const int ak   = (tid & 1) << 3;      // 0 or 8
    const int bk   = tid >> 4;            // 0..15
    const int bn   = (tid & 15) << 3;     // 0..120

    const float* Ag = A + (size_t)(rowBase + arow) * lda + ak;
    const float* Bg = B + (size_t)bk * ldb + colBase + bn;

    float c[2][8][4];
#pragma unroll
    for (int mt = 0; mt < 2; ++mt)
#pragma unroll
        for (int nt = 0; nt < 8; ++nt)
#pragma unroll
            for (int e = 0; e < 4; ++e) c[mt][nt][e] = 0.f;

    float4 av0, av1, bv0, bv1;
    av0 = *(const float4*)(Ag);
    av1 = *(const float4*)(Ag + 4);
    bv0 = *(const float4*)(Bg);
    bv1 = *(const float4*)(Bg + 4);

    const int NIT = 1024 / 16;   // 64

#pragma unroll 1
    for (int kt = 0; kt < NIT; ++kt) {
        *(uint4*)&As[arow * AS_LD + ak] =
            make_uint4(f2tf(av0.x), f2tf(av0.y), f2tf(av0.z), f2tf(av0.w));
        *(uint4*)&As[arow * AS_LD + ak + 4] =
            make_uint4(f2tf(av1.x), f2tf(av1.y), f2tf(av1.z), f2tf(av1.w));
        *(uint4*)&Bs[bk * BS_LD + bn] =
            make_uint4(f2tf(bv0.x), f2tf(bv0.y), f2tf(bv0.z), f2tf(bv0.w));
        *(uint4*)&Bs[bk * BS_LD + bn + 4] =
            make_uint4(f2tf(bv1.x), f2tf(bv1.y), f2tf(bv1.z), f2tf(bv1.w));
        __syncthreads();

        if (kt + 1 < NIT) {
            const float* Ap = Ag + (kt + 1) * 16;
            av0 = *(const float4*)(Ap);
            av1 = *(const float4*)(Ap + 4);
            const float* Bp = Bg + (size_t)(kt + 1) * 16 * ldb;
            bv0 = *(const float4*)(Bp);
            bv1 = *(const float4*)(Bp + 4);
        }

#pragma unroll
        for (int ks = 0; ks < 2; ++ks) {
            unsigned a[2][4];
#pragma unroll
            for (int mt = 0; mt < 2; ++mt) {
                const int r = (wm * 32 + mt * 16 + gid) * AS_LD + ks * 8 + tg;
                a[mt][0] = As[r];
                a[mt][1] = As[r + 8 * AS_LD];
                a[mt][2] = As[r + 4];
                a[mt][3] = As[r + 8 * AS_LD + 4];
            }
#pragma unroll
            for (int nt = 0; nt < 8; ++nt) {
                const int nidx = wn * 64 + nt * 8 + gid;
                const unsigned b0 = Bs[(ks * 8 + tg) * BS_LD + nidx];
                const unsigned b1 = Bs[(ks * 8 + tg + 4) * BS_LD + nidx];
                mma_tf32(c[0][nt], a[0], b0, b1);
                mma_tf32(c[1][nt], a[1], b0, b1);
            }
        }
        __syncthreads();
    }

#pragma unroll
    for (int mt = 0; mt < 2; ++mt) {
#pragma unroll
        for (int nt = 0; nt < 8; ++nt) {
#pragma unroll
            for (int e = 0; e < 4; ++e) {
                const int m   = rowBase + wm * 32 + mt * 16 + gid + (e >> 1) * 8;
                const int col = colBase + wn * 64 + nt * 8 + tg * 2 + (e & 1);
                const float v = c[mt][nt][e];
                if (MODE == 0) {
                    C[(size_t)m * ldc + col] = v + bias[col];
                } else if (MODE == 1) {
                    float s = 1.f / (1.f + expf(-(gdp[(size_t)m * G3 + col] + v)));
                    if (col < D_) {
                        udp[(size_t)m * D_ + col] = s;
                    } else {
                        const int d = col - D_;
                        rxp[(size_t)m * D_ + d] = s * xp[(size_t)m * D_ + d];
                    }
                } else {  // MODE 2
                    float hcd = tanhf(gdp[(size_t)m * G3 + 2 * D_ + col] + v);
                    float xv  = xp[(size_t)m * D_ + col];
                    C[(size_t)m * D_ + col] =
                        fmaf(udp[(size_t)m * D_ + col], hcd - xv, xv);
                }
            }
        }
    }
}

// final_ht = ht[:, T-1, :]
__global__ void __launch_bounds__(256)
copy_final(float* __restrict__ out)
{
    int i = blockIdx.x * 256 + threadIdx.x;          // 0 .. 32767
    int n = i >> 10, h = i & 1023;
    out[i] = g_ht[(size_t)n * TT * H_ + (size_t)(TT - 1) * H_ + h];
}

// ----------------------------------------------------------------------------
extern "C" void kernel_launch(void* const* d_in, const int* in_sizes, int n_in,
                              void* d_out, int out_size)
{
    const float* x      = (const float*)d_in[0];   // (N, T, D)
    const float* state  = (const float*)d_in[1];   // (N, H)
    const float* weight = (const float*)d_in[2];   // (2048, 6144)
    const float* bias   = (const float*)d_in[3];   // (6144,)
    float*       out    = (float*)d_out;           // h (N,T,D) then final_ht (N,H)

    float *gates, *ht, *ud, *rx;
    cudaGetSymbolAddress((void**)&gates, g_gates);
    cudaGetSymbolAddress((void**)&ht,    g_ht);
    cudaGetSymbolAddress((void**)&ud,    g_ud);
    cudaGetSymbolAddress((void**)&rx,    g_rx);

    const dim3 blk(256);
    const int scan_smem = SMEM_FLOATS * 4;   // 199168 B

    cudaFuncSetAttribute(scan_kernel,
                         cudaFuncAttributeMaxDynamicSharedMemorySize, scan_smem);

    // K1: gates = x @ Wxt + bias[:3H]
    tgemm_k<0><<<dim3(G3 / 128, MROWS / 128), blk>>>(
        x, 1024, weight, WLD, bias, gates, G3,
        nullptr, nullptr, nullptr, nullptr);

    // Persistent scan: 512 steps in ONE launch (2 grid barriers per step)
    scan_kernel<<<NBLK_SCAN, blk, scan_smem>>>(weight, state);

    // K3: gd = ht @ Whd + bias[3H:]  (overwrites gates buffer)
    tgemm_k<0><<<dim3(G3 / 128, MROWS / 128), blk>>>(
        ht, 1024, weight + (size_t)D_ * WLD + G3, WLD, bias + G3, gates, G3,
        nullptr, nullptr, nullptr, nullptr);

    // K4: g2 = sigmoid(gd[:, :2D] + x @ Wxd[:, :2D]) -> ud, rx
    tgemm_k<1><<<dim3(2048 / 128, MROWS / 128), blk>>>(
        x, 1024, weight + G3, WLD, nullptr, nullptr, 0,
        gates, x, ud, rx);

    // K5: h = x + ud * (tanh(gd[:, 2D:] + rx @ Wxd[:, 2D:]) - x)
    tgemm_k<2><<<dim3(1024 / 128, MROWS / 128), blk>>>(
        rx, 1024, weight + G3 + 2 * D_, WLD, nullptr, out, D_,
        gates, x, ud, nullptr);

    // final_ht
    copy_final<<<128, blk>>>(out + (size_t)MROWS * D_);
}

// round 10
// speedup vs baseline: 2.3148x; 1.1856x over previous
#include <cuda_runtime.h>
#include <math.h>

// ----------------------------------------------------------------------------
// GridGRU  (D = H = 1024, N = 32, T = 512)
//
// R10: scan matvecs on TF32 tensor cores.
//  * per-warp K-split (128 K each), mma.m16n8k8.tf32, fp32 accum
//  * weight B-fragments register-resident for all 512 steps (rna-converted)
//  * h staged per-warp via cp.async into [n][k] stride-132 tiles
//  * rna-rounded operand copies: g_ht32 (h), g_rh (pre-rounded), g_st32 (state)
//  * gates for step t+1 prefetched during phase B
// GEMMs (TF32 mma) unchanged from R7.
// ----------------------------------------------------------------------------

#define D_    1024
#define H_    1024
#define NB    32
#define TT    512
#define MROWS (NB * TT)     // 16384
#define WLD   6144          // weight row stride (2048 x 6144)
#define G3    3072
#define NBLK_SCAN 128

// Scratch (device globals: allocation-free per harness rules)
__device__ float g_gates[(size_t)MROWS * G3];   // gates, then reused as gd
__device__ float g_ht[(size_t)MROWS * H_];      // ht sequence, fp32 exact
__device__ float g_ht32[(size_t)MROWS * H_];    // ht sequence, rna(tf32)
__device__ float g_st32[NB * H_];               // state, rna(tf32)
__device__ float g_u [NB * H_];                 // per-step u gate (fp32)
__device__ float g_rh[NB * H_];                 // per-step r * h_prev (rna tf32)
__device__ float g_ud[(size_t)MROWS * D_];      // decoder update gate
__device__ float g_rx[(size_t)MROWS * D_];      // rd * x

// ------------------------- software grid barrier ----------------------------
__device__ unsigned int g_bar_count = 0;
__device__ unsigned int g_bar_gen   = 0;

__device__ __forceinline__ void grid_barrier()
{
    __syncthreads();
    __threadfence();
    if (threadIdx.x == 0) {
        unsigned int gen = *(volatile unsigned int*)&g_bar_gen;
        unsigned int tk  = atomicAdd(&g_bar_count, 1u);
        if (tk == NBLK_SCAN - 1) {
            g_bar_count = 0;
            __threadfence();
            *(volatile unsigned int*)&g_bar_gen = gen + 1u;
        } else {
            while (*(volatile unsigned int*)&g_bar_gen == gen) { __nanosleep(32); }
        }
        __threadfence();
    }
    __syncthreads();
}

// ------------------------- small asm helpers --------------------------------
__device__ __forceinline__ unsigned smem_u32(const void* p)
{
    return (unsigned)__cvta_generic_to_shared(p);
}
__device__ __forceinline__ void cp16(unsigned dst, const float* src)
{
    asm volatile("cp.async.cg.shared.global [%0], [%1], 16;" :: "r"(dst), "l"(src));
}
__device__ __forceinline__ void cp_commit()
{
    asm volatile("cp.async.commit_group;");
}
__device__ __forceinline__ void cp_wait0()
{
    asm volatile("cp.async.wait_group 0;");
}
__device__ __forceinline__ unsigned f2tf(float f)
{
    unsigned u;
    asm("cvt.rna.tf32.f32 %0, %1;" : "=r"(u) : "f"(f));
    return u;
}
__device__ __forceinline__ void mma_tf32(float c[4], const unsigned a[4],
                                         unsigned b0, unsigned b1)
{
    asm volatile(
        "mma.sync.aligned.m16n8k8.row.col.f32.tf32.tf32.f32 "
        "{%0,%1,%2,%3}, {%4,%5,%6,%7}, {%8,%9}, {%0,%1,%2,%3};\n"
        : "+f"(c[0]), "+f"(c[1]), "+f"(c[2]), "+f"(c[3])
        : "r"(a[0]), "r"(a[1]), "r"(a[2]), "r"(a[3]), "r"(b0), "r"(b1));
}

// ----------------------------------------------------------------------------
// Scan smem layout (floats):
//   TILE  8 warps x [32][132]  @ 0      (33792)
//   PACC  [8][16][33]          @ 33792  (4224)
//   GSM   [32][20]             @ 38016  (640)   A gates
//   HPE   [32][20]             @ 38656  (640)   A h_prev (r cols, fp32)
//   GSB   [32][12]             @ 39296  (384)   B gates
//   HPB   [32][12]             @ 39680  (384)   B h_prev (fp32)
//   UBB   [32][12]             @ 40064  (384)   B u
// total 40448 floats = 161792 B
// ----------------------------------------------------------------------------
#define TLS      132
#define TILE_F   (32 * TLS)
#define OFF_PACC 33792
#define OFF_GSM  38016
#define OFF_HPE  38656
#define OFF_GSB  39296
#define OFF_HPB  39680
#define OFF_UBB  40064
#define SMEM_FLOATS 40448

extern __shared__ float smem[];

__global__ void __launch_bounds__(256, 1)
scan_kernel(const float* __restrict__ weight, const float* __restrict__ state)
{
    float* PACC = smem + OFF_PACC;
    float* GSM  = smem + OFF_GSM;
    float* HPE  = smem + OFF_HPE;
    float* GSB  = smem + OFF_GSB;
    float* HPB  = smem + OFF_HPB;
    float* UBB  = smem + OFF_UBB;

    const int tid  = threadIdx.x;
    const int b    = blockIdx.x;
    const int lane = tid & 31;
    const int w    = tid >> 5;
    const int gid  = lane >> 2;
    const int tg   = lane & 3;
    const int jbA  = b << 4;
    const int jbB  = b << 3;
    const int k0   = w << 7;            // warp K-slice base

    float* tl = smem + w * TILE_F;
    const unsigned tlu = smem_u32(tl);

    // fragment smem offsets (floats): A rows = batch n
    const int f00 = gid * TLS + tg;            // (gid,   tg)
    const int f01 = (gid + 8) * TLS + tg;      // (gid+8, tg)
    const int m1o = 16 * TLS;

    // ---- preload weight fragments (rna tf32), resident all 512 steps ----
    unsigned bA0[2][16], bA1[2][16], bB0[16], bB1[16];
#pragma unroll
    for (int s = 0; s < 16; ++s) {
        const float* wr = weight + (size_t)(D_ + k0 + 8 * s + tg) * WLD;
#pragma unroll
        for (int nt = 0; nt < 2; ++nt) {
            bA0[nt][s] = f2tf(wr[jbA + nt * 8 + gid]);
            bA1[nt][s] = f2tf(wr[(size_t)4 * WLD + jbA + nt * 8 + gid]);
        }
        bB0[s] = f2tf(wr[2 * H_ + jbB + gid]);
        bB1[s] = f2tf(wr[(size_t)4 * WLD + 2 * H_ + jbB + gid]);
    }

    // prefetch gates(t=0) for phase A
    if (tid < 128) {
        int n = tid >> 2, coff = (tid & 3) << 2;
        cp16(smem_u32(&GSM[n * 20 + coff]),
             g_gates + (size_t)n * TT * G3 + jbA + coff);
    }
    cp_commit();

    for (int t = 0; t < TT; ++t) {
        const float* hp;  size_t hstr;     // fp32 h_prev
        const float* hp32; size_t h32str;  // rna h_prev
        if (t == 0) { hp = state;  hstr = (size_t)H_;
                      hp32 = g_st32; h32str = (size_t)H_; }
        else        { hp = g_ht + (size_t)(t - 1) * H_; hstr = (size_t)TT * H_;
                      hp32 = g_ht32 + (size_t)(t - 1) * H_; h32str = (size_t)TT * H_; }

        // =========================== Phase A ===========================
        // tile: this warp's K-slice of h32, [n][k] stride TLS
        {
            const float* src = hp32 + k0 + (lane << 2);
            const unsigned d0 = tlu + (lane << 4);
#pragma unroll 8
            for (int n = 0; n < 32; ++n)
                cp16(d0 + (unsigned)((n * TLS) << 2), src + (size_t)n * h32str);
        }
        if (tid >= 128 && b >= 64) {   // h_prev (fp32) for r-cols
            int tt2 = tid - 128;
            int n = tt2 >> 2, coff = (tt2 & 3) << 2;
            cp16(smem_u32(&HPE[n * 20 + coff]),
                 hp + (size_t)n * hstr + (jbA - H_) + coff);
        }
        cp_commit();
        cp_wait0();

        float cA[2][2][4];
#pragma unroll
        for (int mt = 0; mt < 2; ++mt)
#pragma unroll
            for (int nt = 0; nt < 2; ++nt)
#pragma unroll
                for (int e = 0; e < 4; ++e) cA[mt][nt][e] = 0.f;

#pragma unroll
        for (int s = 0; s < 16; ++s) {
            const int o = 8 * s;
            unsigned am0[4], am1[4];
            am0[0] = __float_as_uint(tl[f00 + o]);
            am0[1] = __float_as_uint(tl[f01 + o]);
            am0[2] = __float_as_uint(tl[f00 + o + 4]);
            am0[3] = __float_as_uint(tl[f01 + o + 4]);
            am1[0] = __float_as_uint(tl[f00 + m1o + o]);
            am1[1] = __float_as_uint(tl[f01 + m1o + o]);
            am1[2] = __float_as_uint(tl[f00 + m1o + o + 4]);
            am1[3] = __float_as_uint(tl[f01 + m1o + o + 4]);
            mma_tf32(cA[0][0], am0, bA0[0][s], bA1[0][s]);
            mma_tf32(cA[0][1], am0, bA0[1][s], bA1[1][s]);
            mma_tf32(cA[1][0], am1, bA0[0][s], bA1[0][s]);
            mma_tf32(cA[1][1], am1, bA0[1][s], bA1[1][s]);
        }

        // K-partials -> PACC
#pragma unroll
        for (int mt = 0; mt < 2; ++mt)
#pragma unroll
            for (int nt = 0; nt < 2; ++nt)
#pragma unroll
                for (int e = 0; e < 4; ++e) {
                    int row = mt * 16 + gid + ((e >> 1) << 3);
                    int col = nt * 8 + 2 * tg + (e & 1);
                    PACC[w * 528 + col * 33 + row] = cA[mt][nt][e];
                }
        __syncthreads();

        // combine + sigmoid + store u / rh (rh stored rna-rounded)
        {
            float* dst = (b < 64) ? g_u : g_rh;
            const int jb0 = (b < 64) ? jbA : (jbA - H_);
#pragma unroll
            for (int s2 = 0; s2 < 2; ++s2) {
                int idx = tid + (s2 << 8);
                int c = idx & 15, n = idx >> 4;
                float z = GSM[n * 20 + c];
#pragma unroll
                for (int g = 0; g < 8; ++g) z += PACC[g * 528 + c * 33 + n];
                float s = 1.f / (1.f + expf(-z));
                float o;
                if (b < 64) o = s;
                else        o = __uint_as_float(f2tf(s * HPE[n * 20 + c]));
                dst[n * H_ + jb0 + c] = o;
            }
        }
        // pre-barrier staging for phase B (gates + h_prev)
        if (tid < 64) {
            int n = tid >> 1, coff = (tid & 1) << 2;
            cp16(smem_u32(&GSB[n * 12 + coff]),
                 g_gates + (size_t)n * TT * G3 + (size_t)t * G3 + 2 * H_ + jbB + coff);
        } else if (tid < 128) {
            int tt2 = tid - 64;
            int n = tt2 >> 1, coff = (tt2 & 1) << 2;
            cp16(smem_u32(&HPB[n * 12 + coff]),
                 hp + (size_t)n * hstr + jbB + coff);
        }
        cp_commit();
        grid_barrier();

        // =========================== Phase B ===========================
        {
            const float* src = g_rh + k0 + (lane << 2);
            const unsigned d0 = tlu + (lane << 4);
#pragma unroll 8
            for (int n = 0; n < 32; ++n)
                cp16(d0 + (unsigned)((n * TLS) << 2), src + n * H_);
        }
        if (tid < 64) {
            int n = tid >> 1, coff = (tid & 1) << 2;
            cp16(smem_u32(&UBB[n * 12 + coff]), g_u + n * H_ + jbB + coff);
        }
        cp_commit();
        cp_wait0();

        float cB[2][4];
#pragma unroll
        for (int mt = 0; mt < 2; ++mt)
#pragma unroll
            for (int e = 0; e < 4; ++e) cB[mt][e] = 0.f;

#pragma unroll
        for (int s = 0; s < 16; ++s) {
            const int o = 8 * s;
            unsigned am0[4], am1[4];
            am0[0] = __float_as_uint(tl[f00 + o]);
            am0[1] = __float_as_uint(tl[f01 + o]);
            am0[2] = __float_as_uint(tl[f00 + o + 4]);
            am0[3] = __float_as_uint(tl[f01 + o + 4]);
            am1[0] = __float_as_uint(tl[f00 + m1o + o]);
            am1[1] = __float_as_uint(tl[f01 + m1o + o]);
            am1[2] = __float_as_uint(tl[f00 + m1o + o + 4]);
            am1[3] = __float_as_uint(tl[f01 + m1o + o + 4]);
            mma_tf32(cB[0], am0, bB0[s], bB1[s]);
            mma_tf32(cB[1], am1, bB0[s], bB1[s]);
        }

#pragma unroll
        for (int mt = 0; mt < 2; ++mt)
#pragma unroll
            for (int e = 0; e < 4; ++e) {
                int row = mt * 16 + gid + ((e >> 1) << 3);
                int col = 2 * tg + (e & 1);
                PACC[w * 528 + col * 33 + row] = cB[mt][e];
            }
        __syncthreads();

        // combine + tanh + h update; store fp32 h and rna copy
        if (tid < 256) {
            int c = tid & 7, n = tid >> 3;
            float z = GSB[n * 12 + c];
#pragma unroll
            for (int g = 0; g < 8; ++g) z += PACC[g * 528 + c * 33 + n];
            float hc = tanhf(z);
            float hv = HPB[n * 12 + c];
            float u  = UBB[n * 12 + c];
            float h  = fmaf(u, hc - hv, hv);
            size_t off = (size_t)n * TT * H_ + (size_t)t * H_ + jbB + c;
            g_ht[off]   = h;
            g_ht32[off] = __uint_as_float(f2tf(h));
        }
        // prefetch gates(t+1) for next phase A
        if (t + 1 < TT && tid < 128) {
            int n = tid >> 2, coff = (tid & 3) << 2;
            cp16(smem_u32(&GSM[n * 20 + coff]),
                 g_gates + (size_t)n * TT * G3 + (size_t)(t + 1) * G3 + jbA + coff);
        }
        cp_commit();
        grid_barrier();
    }
}

// state -> rna(tf32) copy
__global__ void __launch_bounds__(256)
state32_kernel(const float* __restrict__ state)
{
    int i = blockIdx.x * 256 + threadIdx.x;   // 0..32767
    g_st32[i] = __uint_as_float(f2tf(state[i]));
}

// ----------------------------------------------------------------------------
// TF32 tensor-core GEMM (unchanged from R7).
// ----------------------------------------------------------------------------
#define AS_LD 20
#define BS_LD 136

template <int MODE>
__global__ void __launch_bounds__(256, 2)
tgemm_k(const float* __restrict__ A, int lda,
        const float* __restrict__ B, int ldb,
        const float* __restrict__ bias,
        float* __restrict__ C, int ldc,
        const float* __restrict__ gdp,
        const float* __restrict__ xp,
        float* __restrict__ udp,
        float* __restrict__ rxp)
{
    __shared__ __align__(16) unsigned As[128 * AS_LD];   // [m][k]
    __shared__ __align__(16) unsigned Bs[16 * BS_LD];    // [k][n]

    const int tid  = threadIdx.x;
    const int lane = tid & 31;
    const int warp = tid >> 5;
    const int gid  = lane >> 2;
    const int tg   = lane & 3;
    const int wm   = warp & 3;
    const int wn   = warp >> 2;

    const int rowBase = blockIdx.y << 7;
    const int colBase = blockIdx.x << 7;

    const int arow = tid >> 1;
    const int ak   = (tid & 1) << 3;
    const int bk   = tid >> 4;
    const int bn   = (tid & 15) << 3;

    const float* Ag = A + (size_t)(rowBase + arow) * lda + ak;
    const float* Bg = B + (size_t)bk * ldb + colBase + bn;

    float c[2][8][4];
#pragma unroll
    for (int mt = 0; mt < 2; ++mt)
#pragma unroll
        for (int nt = 0; nt < 8; ++nt)
#pragma unroll
            for (int e = 0; e < 4; ++e) c[mt][nt][e] = 0.f;

    float4 av0, av1, bv0, bv1;
    av0 = *(const float4*)(Ag);
    av1 = *(const float4*)(Ag + 4);
    bv0 = *(const float4*)(Bg);
    bv1 = *(const float4*)(Bg + 4);

    const int NIT = 1024 / 16;

#pragma unroll 1
    for (int kt = 0; kt < NIT; ++kt) {
        *(uint4*)&As[arow * AS_LD + ak] =
            make_uint4(f2tf(av0.x), f2tf(av0.y), f2tf(av0.z), f2tf(av0.w));
        *(uint4*)&As[arow * AS_LD + ak + 4] =
            make_uint4(f2tf(av1.x), f2tf(av1.y), f2tf(av1.z), f2tf(av1.w));
        *(uint4*)&Bs[bk * BS_LD + bn] =
            make_uint4(f2tf(bv0.x), f2tf(bv0.y), f2tf(bv0.z), f2tf(bv0.w));
        *(uint4*)&Bs[bk * BS_LD + bn + 4] =
            make_uint4(f2tf(bv1.x), f2tf(bv1.y), f2tf(bv1.z), f2tf(bv1.w));
        __syncthreads();

        if (kt + 1 < NIT) {
            const float* Ap = Ag + (kt + 1) * 16;
            av0 = *(const float4*)(Ap);
            av1 = *(const float4*)(Ap + 4);
            const float* Bp = Bg + (size_t)(kt + 1) * 16 * ldb;
            bv0 = *(const float4*)(Bp);
            bv1 = *(const float4*)(Bp + 4);
        }

#pragma unroll
        for (int ks = 0; ks < 2; ++ks) {
            unsigned a[2][4];
#pragma unroll
            for (int mt = 0; mt < 2; ++mt) {
                const int r = (wm * 32 + mt * 16 + gid) * AS_LD + ks * 8 + tg;
                a[mt][0] = As[r];
                a[mt][1] = As[r + 8 * AS_LD];
                a[mt][2] = As[r + 4];
                a[mt][3] = As[r + 8 * AS_LD + 4];
            }
#pragma unroll
            for (int nt = 0; nt < 8; ++nt) {
                const int nidx = wn * 64 + nt * 8 + gid;
                const unsigned b0 = Bs[(ks * 8 + tg) * BS_LD + nidx];
                const unsigned b1 = Bs[(ks * 8 + tg + 4) * BS_LD + nidx];
                mma_tf32(c[0][nt], a[0], b0, b1);
                mma_tf32(c[1][nt], a[1], b0, b1);
            }
        }
        __syncthreads();
    }

#pragma unroll
    for (int mt = 0; mt < 2; ++mt) {
#pragma unroll
        for (int nt = 0; nt < 8; ++nt) {
#pragma unroll
            for (int e = 0; e < 4; ++e) {
                const int m   = rowBase + wm * 32 + mt * 16 + gid + (e >> 1) * 8;
                const int col = colBase + wn * 64 + nt * 8 + tg * 2 + (e & 1);
                const float v = c[mt][nt][e];
                if (MODE == 0) {
                    C[(size_t)m * ldc + col] = v + bias[col];
                } else if (MODE == 1) {
                    float s = 1.f / (1.f + expf(-(gdp[(size_t)m * G3 + col] + v)));
                    if (col < D_) {
                        udp[(size_t)m * D_ + col] = s;
                    } else {
                        const int d = col - D_;
                        rxp[(size_t)m * D_ + d] = s * xp[(size_t)m * D_ + d];
                    }
                } else {
                    float hcd = tanhf(gdp[(size_t)m * G3 + 2 * D_ + col] + v);
                    float xv  = xp[(size_t)m * D_ + col];
                    C[(size_t)m * D_ + col] =
                        fmaf(udp[(size_t)m * D_ + col], hcd - xv, xv);
                }
            }
        }
    }
}

// final_ht = ht[:, T-1, :]
__global__ void __launch_bounds__(256)
copy_final(float* __restrict__ out)
{
    int i = blockIdx.x * 256 + threadIdx.x;
    int n = i >> 10, h = i & 1023;
    out[i] = g_ht[(size_t)n * TT * H_ + (size_t)(TT - 1) * H_ + h];
}

// ----------------------------------------------------------------------------
extern "C" void kernel_launch(void* const* d_in, const int* in_sizes, int n_in,
                              void* d_out, int out_size)
{
    const float* x      = (const float*)d_in[0];
    const float* state  = (const float*)d_in[1];
    const float* weight = (const float*)d_in[2];
    const float* bias   = (const float*)d_in[3];
    float*       out    = (float*)d_out;

    float *gates, *ht, *ud, *rx;
    cudaGetSymbolAddress((void**)&gates, g_gates);
    cudaGetSymbolAddress((void**)&ht,    g_ht);
    cudaGetSymbolAddress((void**)&ud,    g_ud);
    cudaGetSymbolAddress((void**)&rx,    g_rx);

    const dim3 blk(256);
    const int scan_smem = SMEM_FLOATS * 4;   // 161792 B

    cudaFuncSetAttribute(scan_kernel,
                         cudaFuncAttributeMaxDynamicSharedMemorySize, scan_smem);

    // K1: gates = x @ Wxt + bias[:3H]
    tgemm_k<0><<<dim3(G3 / 128, MROWS / 128), blk>>>(
        x, 1024, weight, WLD, bias, gates, G3,
        nullptr, nullptr, nullptr, nullptr);

    // rna-rounded state copy for the tensor-core scan
    state32_kernel<<<128, blk>>>(state);

    // Persistent scan: 512 steps in ONE launch
    scan_kernel<<<NBLK_SCAN, blk, scan_smem>>>(weight, state);

    // K3: gd = ht @ Whd + bias[3H:]
    tgemm_k<0><<<dim3(G3 / 128, MROWS / 128), blk>>>(
        ht, 1024, weight + (size_t)D_ * WLD + G3, WLD, bias + G3, gates, G3,
        nullptr, nullptr, nullptr, nullptr);

    // K4: g2 = sigmoid(gd[:, :2D] + x @ Wxd[:, :2D]) -> ud, rx
    tgemm_k<1><<<dim3(2048 / 128, MROWS / 128), blk>>>(
        x, 1024, weight + G3, WLD, nullptr, nullptr, 0,
        gates, x, ud, rx);

    // K5: h = x + ud * (tanh(gd[:, 2D:] + rx @ Wxd[:, 2D:]) - x)
    tgemm_k<2><<<dim3(1024 / 128, MROWS / 128), blk>>>(
        rx, 1024, weight + G3 + 2 * D_, WLD, nullptr, out, D_,
        gates, x, ud, nullptr);

    // final_ht
    copy_final<<<128, blk>>>(out + (size_t)MROWS * D_);
}